// round 4
// baseline (speedup 1.0000x reference)
#include <cuda_runtime.h>
#include <cstdint>
#include <cstddef>

#define Bc 2
#define Hc 128
#define Wc 128
#define Cc 256
#define C3 768
#define NPIX (Bc*Hc*Wc)           // 32768
#define HEADS 8
#define HD 32
#define WS 8
#define KW 16
#define NWIN 512                  // B * 16 * 16

// ---------------- scratch (device globals; no allocation) ----------------
__device__ __align__(16) float g_qkv [(size_t)NPIX * C3];   // after GEMM
__device__ __align__(16) float g_qkv2[(size_t)NPIX * C3];   // after conv+LN+bias
__device__ __align__(16) float g_att [(size_t)NPIX * Cc];   // attention out (B,H,W,C)
__device__ __align__(16) float g_bias_tab[529 * 8];
__device__ float g_scale[8];

// ---------------- CPB MLP + per-head scale ----------------
__global__ void cpb_kernel(const float* __restrict__ w1, const float* __restrict__ b1,
                           const float* __restrict__ w2, const float* __restrict__ ls)
{
    int t = blockIdx.x * blockDim.x + threadIdx.x;
    if (t < 8) g_scale[t] = expf(fminf(ls[t], 4.605170185988091f)); // log(100)
    if (t >= 529) return;
    int a = t / 23, b = t % 23;
    float c0 = (float)(a - 11) * (8.0f / 7.0f);
    float c1 = (float)(b - 11) * (8.0f / 7.0f);
    const float inv_log8 = 0.4808983469629878f; // 1/ln(8)
    float v0 = copysignf(log1pf(fabsf(c0)), c0) * inv_log8;
    float v1 = copysignf(log1pf(fabsf(c1)), c1) * inv_log8;
    float acc[8];
#pragma unroll
    for (int h = 0; h < 8; h++) acc[h] = 0.f;
    for (int j = 0; j < 512; j++) {
        float hv = fmaxf(fmaf(v0, w1[j], fmaf(v1, w1[512 + j], b1[j])), 0.f);
#pragma unroll
        for (int h = 0; h < 8; h++) acc[h] += hv * w2[j * 8 + h];
    }
#pragma unroll
    for (int h = 0; h < 8; h++)
        g_bias_tab[t * 8 + h] = 16.0f / (1.0f + expf(-acc[h]));
}

// ---------------- classic 128x128x8 fp32 SGEMM (M,N,K all multiples of 128/128/8) ----------------
__global__ __launch_bounds__(256) void sgemm128(const float* __restrict__ A,
                                                const float* __restrict__ B,
                                                float* __restrict__ C,
                                                int M, int N, int K)
{
    __shared__ float As[8][128];
    __shared__ float Bs[8][128];
    int tid = threadIdx.x;
    int bx = blockIdx.x, by = blockIdx.y;
    int arow = tid >> 1,  acol = (tid & 1) << 2;
    int brow = tid >> 5,  bcol = (tid & 31) << 2;
    int tx = tid & 15, ty = tid >> 4;
    const float* Aptr = A + (size_t)(by * 128 + arow) * K + acol;
    const float* Bptr = B + (size_t)brow * N + bx * 128 + bcol;

    float acc[8][8];
#pragma unroll
    for (int i = 0; i < 8; i++)
#pragma unroll
        for (int j = 0; j < 8; j++) acc[i][j] = 0.f;

    for (int k0 = 0; k0 < K; k0 += 8) {
        float4 a4 = *reinterpret_cast<const float4*>(Aptr + k0);
        As[acol + 0][arow] = a4.x;
        As[acol + 1][arow] = a4.y;
        As[acol + 2][arow] = a4.z;
        As[acol + 3][arow] = a4.w;
        *reinterpret_cast<float4*>(&Bs[brow][bcol]) =
            *reinterpret_cast<const float4*>(Bptr + (size_t)k0 * N);
        __syncthreads();
#pragma unroll
        for (int kk = 0; kk < 8; kk++) {
            float ar[8], br[8];
            *reinterpret_cast<float4*>(&ar[0]) = *reinterpret_cast<const float4*>(&As[kk][ty * 8]);
            *reinterpret_cast<float4*>(&ar[4]) = *reinterpret_cast<const float4*>(&As[kk][ty * 8 + 4]);
            *reinterpret_cast<float4*>(&br[0]) = *reinterpret_cast<const float4*>(&Bs[kk][tx * 8]);
            *reinterpret_cast<float4*>(&br[4]) = *reinterpret_cast<const float4*>(&Bs[kk][tx * 8 + 4]);
#pragma unroll
            for (int i = 0; i < 8; i++)
#pragma unroll
                for (int j = 0; j < 8; j++)
                    acc[i][j] = fmaf(ar[i], br[j], acc[i][j]);
        }
        __syncthreads();
    }
    float* Cp = C + (size_t)(by * 128 + ty * 8) * N + bx * 128 + tx * 8;
#pragma unroll
    for (int i = 0; i < 8; i++) {
        *reinterpret_cast<float4*>(Cp + (size_t)i * N)     = make_float4(acc[i][0], acc[i][1], acc[i][2], acc[i][3]);
        *reinterpret_cast<float4*>(Cp + (size_t)i * N + 4) = make_float4(acc[i][4], acc[i][5], acc[i][6], acc[i][7]);
    }
}

// ---------------- depthwise 3x3 conv + LayerNorm + qkv bias (fused) ----------------
__global__ __launch_bounds__(256) void convln_kernel(const float* __restrict__ qkv,
                                                     const float* __restrict__ wdw,
                                                     const float* __restrict__ lng,
                                                     const float* __restrict__ lnb,
                                                     const float* __restrict__ qb,
                                                     const float* __restrict__ vb,
                                                     float* __restrict__ out)
{
    int p  = blockIdx.x;
    int b  = p >> 14;
    int hh = (p >> 7) & 127;
    int ww = p & 127;
    int tid = threadIdx.x;

    float acc[3];
#pragma unroll
    for (int cc = 0; cc < 3; cc++) {
        int c = tid + cc * 256;
        float a = 0.f;
#pragma unroll
        for (int dh = -1; dh <= 1; dh++) {
            int rr = hh + dh;
            if (rr < 0 || rr > 127) continue;
#pragma unroll
            for (int dw = -1; dw <= 1; dw++) {
                int col = ww + dw;
                if (col < 0 || col > 127) continue;
                a = fmaf(qkv[((size_t)((b * 128 + rr) * 128 + col)) * C3 + c],
                         wdw[((dh + 1) * 3 + (dw + 1)) * C3 + c], a);
            }
        }
        acc[cc] = a;
    }
    float s  = acc[0] + acc[1] + acc[2];
    float sq = acc[0] * acc[0] + acc[1] * acc[1] + acc[2] * acc[2];
#pragma unroll
    for (int off = 16; off > 0; off >>= 1) {
        s  += __shfl_xor_sync(0xffffffffu, s,  off);
        sq += __shfl_xor_sync(0xffffffffu, sq, off);
    }
    __shared__ float reds[8], redq[8];
    int wid = tid >> 5, lane = tid & 31;
    if (lane == 0) { reds[wid] = s; redq[wid] = sq; }
    __syncthreads();
    float st = 0.f, sqt = 0.f;
#pragma unroll
    for (int i = 0; i < 8; i++) { st += reds[i]; sqt += redq[i]; }
    float mu   = st * (1.0f / 768.0f);
    float var  = sqt * (1.0f / 768.0f) - mu * mu;
    float rstd = rsqrtf(var + 1e-5f);

    size_t base = (size_t)p * C3;
#pragma unroll
    for (int cc = 0; cc < 3; cc++) {
        int c = tid + cc * 256;
        float y = (acc[cc] - mu) * rstd * lng[c] + lnb[c];
        if (c < 256)       y += qb[c];
        else if (c >= 512) y += vb[c - 512];
        out[base + c] = y;
    }
}

// ---------------- fused windowed cosine attention ----------------
// grid (512 windows, 8 heads), 128 threads: tid&63 = query, tid>>6 = key-half
__global__ __launch_bounds__(128) void attn_kernel(const float* __restrict__ qkv2,
                                                   float* __restrict__ out)
{
    extern __shared__ float sm[];
    float* Ks = sm;              // 256*32
    float* Vs = sm + 256 * 32;   // 256*32

    int widx = blockIdx.x;
    int h    = blockIdx.y;
    int b  = widx >> 8;
    int wr = (widx >> 4) & 15;
    int wc = widx & 15;
    int tid = threadIdx.x;

    int base_r = wr * 8 - 4, base_c = wc * 8 - 4;
    // load K/V tiles (zero-padded halo)
    for (int i = tid; i < 256 * 8; i += 128) {
        int k  = i >> 3, d4 = i & 7;
        int kr = k >> 4, kc = k & 15;
        int gr = base_r + kr, gc = base_c + kc;
        float4 kv = make_float4(0.f, 0.f, 0.f, 0.f);
        float4 vv = make_float4(0.f, 0.f, 0.f, 0.f);
        if (gr >= 0 && gr < 128 && gc >= 0 && gc < 128) {
            const float* p = qkv2 + ((size_t)((b * 128 + gr) * 128 + gc)) * C3 + 256 + h * HD + d4 * 4;
            kv = *reinterpret_cast<const float4*>(p);
            vv = *reinterpret_cast<const float4*>(p + 256);
        }
        *reinterpret_cast<float4*>(Ks + k * HD + d4 * 4) = kv;
        *reinterpret_cast<float4*>(Vs + k * HD + d4 * 4) = vv;
    }
    __syncthreads();
    // l2-normalize K rows (2 rows per thread)
    for (int k = tid; k < 256; k += 128) {
        float* row = Ks + k * HD;
        float ss = 0.f;
#pragma unroll
        for (int d = 0; d < HD; d++) ss = fmaf(row[d], row[d], ss);
        float r = rsqrtf(fmaxf(ss, 1.55e-5f));
#pragma unroll
        for (int d = 0; d < HD; d++) row[d] *= r;
    }

    // q row for this thread (normalized * per-head scale)
    int qq = tid & 63, half = tid >> 6;
    int qr = qq >> 3, qc = qq & 7;
    int pr = wr * 8 + qr, pc = wc * 8 + qc;
    const float* qp = qkv2 + ((size_t)((b * 128 + pr) * 128 + pc)) * C3 + h * HD;
    float qreg[HD];
    float ssq = 0.f;
#pragma unroll
    for (int d = 0; d < HD; d++) { qreg[d] = qp[d]; ssq = fmaf(qreg[d], qreg[d], ssq); }
    float qmul = rsqrtf(fmaxf(ssq, 1.55e-5f)) * g_scale[h];
#pragma unroll
    for (int d = 0; d < HD; d++) qreg[d] *= qmul;

    __syncthreads();  // K normalization visible

    float o[HD];
#pragma unroll
    for (int d = 0; d < HD; d++) o[d] = 0.f;
    float l = 0.f;

    int k0 = half * 128;
    for (int k = k0; k < k0 + 128; k++) {
        const float* kv = Ks + k * HD;
        float s0 = 0.f, s1 = 0.f, s2 = 0.f, s3 = 0.f;
#pragma unroll
        for (int d = 0; d < HD; d += 4) {
            s0 = fmaf(qreg[d + 0], kv[d + 0], s0);
            s1 = fmaf(qreg[d + 1], kv[d + 1], s1);
            s2 = fmaf(qreg[d + 2], kv[d + 2], s2);
            s3 = fmaf(qreg[d + 3], kv[d + 3], s3);
        }
        int kr = k >> 4, kc = k & 15;
        int idx = (qr - kr + 15) * 23 + (qc - kc + 15);
        float sc = (s0 + s1) + (s2 + s3) + g_bias_tab[idx * 8 + h];
        // scores bounded: |cos|*10 + bias in [0,16] -> sc in [-10,26]; shift by 16, no max needed
        float pw = __expf(sc - 16.0f);
        l += pw;
        const float* vv = Vs + k * HD;
#pragma unroll
        for (int d = 0; d < HD; d++) o[d] = fmaf(pw, vv[d], o[d]);
    }
    __syncthreads();  // done with Ks/Vs; reuse Ks as merge scratch
    float* scratch = Ks;  // 64 * 33 floats needed, fits
    if (half == 1) {
        scratch[qq * 33 + 32] = l;
#pragma unroll
        for (int d = 0; d < HD; d++) scratch[qq * 33 + d] = o[d];
    }
    __syncthreads();
    if (half == 0) {
        l += scratch[qq * 33 + 32];
        float inv = 1.0f / l;
        float* op = out + ((size_t)((b * 128 + pr) * 128 + pc)) * Cc + h * HD;
#pragma unroll
        for (int d = 0; d < HD; d++) op[d] = (o[d] + scratch[qq * 33 + d]) * inv;
    }
}

// ---------------- launch ----------------
extern "C" void kernel_launch(void* const* d_in, const int* in_sizes, int n_in,
                              void* d_out, int out_size)
{
    const float* x           = (const float*)d_in[0];
    const float* w_qkv       = (const float*)d_in[1];
    const float* w_dw        = (const float*)d_in[2];
    const float* ln_g        = (const float*)d_in[3];
    const float* ln_b        = (const float*)d_in[4];
    const float* q_bias      = (const float*)d_in[5];
    const float* v_bias      = (const float*)d_in[6];
    const float* logit_scale = (const float*)d_in[7];
    const float* cpb_w1      = (const float*)d_in[8];
    const float* cpb_b1      = (const float*)d_in[9];
    const float* cpb_w2      = (const float*)d_in[10];
    const float* w_proj      = (const float*)d_in[11];
    float* out = (float*)d_out;

    float *p_qkv, *p_qkv2, *p_att;
    cudaGetSymbolAddress((void**)&p_qkv,  g_qkv);
    cudaGetSymbolAddress((void**)&p_qkv2, g_qkv2);
    cudaGetSymbolAddress((void**)&p_att,  g_att);

    cudaFuncSetAttribute(attn_kernel, cudaFuncAttributeMaxDynamicSharedMemorySize, 65536);

    // 1) CPB bias table + per-head scales (tiny)
    cpb_kernel<<<5, 128>>>(cpb_w1, cpb_b1, cpb_w2, logit_scale);

    // 2) qkv = x @ w_qkv   [32768 x 256] @ [256 x 768]
    sgemm128<<<dim3(C3 / 128, NPIX / 128), 256>>>(x, w_qkv, p_qkv, NPIX, C3, Cc);

    // 3) depthwise conv + LN + bias
    convln_kernel<<<NPIX, 256>>>(p_qkv, w_dw, ln_g, ln_b, q_bias, v_bias, p_qkv2);

    // 4) fused windowed attention
    attn_kernel<<<dim3(NWIN, HEADS), 128, 65536>>>(p_qkv2, p_att);

    // 5) out = att @ w_proj   [32768 x 256] @ [256 x 256]
    sgemm128<<<dim3(Cc / 128, NPIX / 128), 256>>>(p_att, w_proj, out, NPIX, Cc, Cc);
}

// round 7
// speedup vs baseline: 1.2825x; 1.2825x over previous
#include <cuda_runtime.h>
#include <cstdint>
#include <cstddef>

#define Bc 2
#define Hc 128
#define Wc 128
#define Cc 256
#define C3 768
#define NPIX (Bc*Hc*Wc)           // 32768
#define HEADS 8
#define HD 32
#define WS 8
#define KW 16
#define NWIN 512                  // B * 16 * 16

// smem strides (floats) chosen for bank-conflict-free access
#define QT_S 72    // Qt[32][QT_S]  (float4-aligned, broadcast reads)
#define KT_S 133   // Kt[32][KT_S]  (odd -> conflict-free scalar r/w)
#define V_S  40    // Vs[128][V_S]  (float4-aligned)
#define PT_S 65    // Pt[128][PT_S] (odd -> conflict-free scalar r/w)
#define QR_S 36    // Qraw/Obuf[64][QR_S]

// ---------------- scratch (device globals; no allocation) ----------------
__device__ __align__(16) float g_qkv [(size_t)NPIX * C3];   // after GEMM
__device__ __align__(16) float g_qkv2[(size_t)NPIX * C3];   // after conv+LN+bias
__device__ __align__(16) float g_att [(size_t)NPIX * Cc];   // attention out (B,H,W,C)
__device__ __align__(16) float g_bias_tab[8 * 529];         // head-major
__device__ float g_scale[8];

// ---------------- CPB MLP + per-head scale ----------------
__global__ void cpb_kernel(const float* __restrict__ w1, const float* __restrict__ b1,
                           const float* __restrict__ w2, const float* __restrict__ ls)
{
    int t = blockIdx.x * blockDim.x + threadIdx.x;
    if (t < 8) g_scale[t] = expf(fminf(ls[t], 4.605170185988091f)); // log(100)
    if (t >= 529) return;
    int a = t / 23, b = t % 23;
    float c0 = (float)(a - 11) * (8.0f / 7.0f);
    float c1 = (float)(b - 11) * (8.0f / 7.0f);
    const float inv_log8 = 0.4808983469629878f; // 1/ln(8)
    float v0 = copysignf(log1pf(fabsf(c0)), c0) * inv_log8;
    float v1 = copysignf(log1pf(fabsf(c1)), c1) * inv_log8;
    float acc[8];
#pragma unroll
    for (int h = 0; h < 8; h++) acc[h] = 0.f;
    for (int j = 0; j < 512; j++) {
        float hv = fmaxf(fmaf(v0, w1[j], fmaf(v1, w1[512 + j], b1[j])), 0.f);
#pragma unroll
        for (int h = 0; h < 8; h++) acc[h] += hv * w2[j * 8 + h];
    }
#pragma unroll
    for (int h = 0; h < 8; h++)
        g_bias_tab[h * 529 + t] = 16.0f / (1.0f + expf(-acc[h]));
}

// ---------------- classic 128x128x8 fp32 SGEMM with register-staged prefetch ----------------
__global__ __launch_bounds__(256) void sgemm128(const float* __restrict__ A,
                                                const float* __restrict__ B,
                                                float* __restrict__ C,
                                                int M, int N, int K)
{
    __shared__ float As[8][128];
    __shared__ float Bs[8][128];
    int tid = threadIdx.x;
    int bx = blockIdx.x, by = blockIdx.y;
    int arow = tid >> 1,  acol = (tid & 1) << 2;
    int brow = tid >> 5,  bcol = (tid & 31) << 2;
    int tx = tid & 15, ty = tid >> 4;
    const float* Aptr = A + (size_t)(by * 128 + arow) * K + acol;
    const float* Bptr = B + (size_t)brow * N + bx * 128 + bcol;

    float acc[8][8];
#pragma unroll
    for (int i = 0; i < 8; i++)
#pragma unroll
        for (int j = 0; j < 8; j++) acc[i][j] = 0.f;

    float4 a4 = *reinterpret_cast<const float4*>(Aptr);
    float4 b4 = *reinterpret_cast<const float4*>(Bptr);

    for (int k0 = 0; k0 < K; k0 += 8) {
        As[acol + 0][arow] = a4.x;
        As[acol + 1][arow] = a4.y;
        As[acol + 2][arow] = a4.z;
        As[acol + 3][arow] = a4.w;
        *reinterpret_cast<float4*>(&Bs[brow][bcol]) = b4;
        __syncthreads();
        if (k0 + 8 < K) {   // prefetch next slice while computing this one
            a4 = *reinterpret_cast<const float4*>(Aptr + k0 + 8);
            b4 = *reinterpret_cast<const float4*>(Bptr + (size_t)(k0 + 8) * N);
        }
#pragma unroll
        for (int kk = 0; kk < 8; kk++) {
            float ar[8], br[8];
            *reinterpret_cast<float4*>(&ar[0]) = *reinterpret_cast<const float4*>(&As[kk][ty * 8]);
            *reinterpret_cast<float4*>(&ar[4]) = *reinterpret_cast<const float4*>(&As[kk][ty * 8 + 4]);
            *reinterpret_cast<float4*>(&br[0]) = *reinterpret_cast<const float4*>(&Bs[kk][tx * 8]);
            *reinterpret_cast<float4*>(&br[4]) = *reinterpret_cast<const float4*>(&Bs[kk][tx * 8 + 4]);
#pragma unroll
            for (int i = 0; i < 8; i++)
#pragma unroll
                for (int j = 0; j < 8; j++)
                    acc[i][j] = fmaf(ar[i], br[j], acc[i][j]);
        }
        __syncthreads();
    }
    float* Cp = C + (size_t)(by * 128 + ty * 8) * N + bx * 128 + tx * 8;
#pragma unroll
    for (int i = 0; i < 8; i++) {
        *reinterpret_cast<float4*>(Cp + (size_t)i * N)     = make_float4(acc[i][0], acc[i][1], acc[i][2], acc[i][3]);
        *reinterpret_cast<float4*>(Cp + (size_t)i * N + 4) = make_float4(acc[i][4], acc[i][5], acc[i][6], acc[i][7]);
    }
}

// ---------------- depthwise 3x3 conv + LayerNorm + qkv bias (fused) ----------------
__global__ __launch_bounds__(256) void convln_kernel(const float* __restrict__ qkv,
                                                     const float* __restrict__ wdw,
                                                     const float* __restrict__ lng,
                                                     const float* __restrict__ lnb,
                                                     const float* __restrict__ qb,
                                                     const float* __restrict__ vb,
                                                     float* __restrict__ out)
{
    int p  = blockIdx.x;
    int b  = p >> 14;
    int hh = (p >> 7) & 127;
    int ww = p & 127;
    int tid = threadIdx.x;

    float acc[3];
#pragma unroll
    for (int cc = 0; cc < 3; cc++) {
        int c = tid + cc * 256;
        float a = 0.f;
#pragma unroll
        for (int dh = -1; dh <= 1; dh++) {
            int rr = hh + dh;
            if (rr < 0 || rr > 127) continue;
#pragma unroll
            for (int dw = -1; dw <= 1; dw++) {
                int col = ww + dw;
                if (col < 0 || col > 127) continue;
                a = fmaf(qkv[((size_t)((b * 128 + rr) * 128 + col)) * C3 + c],
                         wdw[((dh + 1) * 3 + (dw + 1)) * C3 + c], a);
            }
        }
        acc[cc] = a;
    }
    float s  = acc[0] + acc[1] + acc[2];
    float sq = acc[0] * acc[0] + acc[1] * acc[1] + acc[2] * acc[2];
#pragma unroll
    for (int off = 16; off > 0; off >>= 1) {
        s  += __shfl_xor_sync(0xffffffffu, s,  off);
        sq += __shfl_xor_sync(0xffffffffu, sq, off);
    }
    __shared__ float reds[8], redq[8];
    int wid = tid >> 5, lane = tid & 31;
    if (lane == 0) { reds[wid] = s; redq[wid] = sq; }
    __syncthreads();
    float st = 0.f, sqt = 0.f;
#pragma unroll
    for (int i = 0; i < 8; i++) { st += reds[i]; sqt += redq[i]; }
    float mu   = st * (1.0f / 768.0f);
    float var  = sqt * (1.0f / 768.0f) - mu * mu;
    float rstd = rsqrtf(var + 1e-5f);

    size_t base = (size_t)p * C3;
#pragma unroll
    for (int cc = 0; cc < 3; cc++) {
        int c = tid + cc * 256;
        float y = (acc[cc] - mu) * rstd * lng[c] + lnb[c];
        if (c < 256)       y += qb[c];
        else if (c >= 512) y += vb[c - 512];
        out[base + c] = y;
    }
}

// ---------------- fused windowed cosine attention (register-tiled GEMMs) ----------------
// grid (512 windows, 8 heads), 256 threads.
// Per half (128 keys): S-GEMM (8q x 4k tiles), exp+bias, PV-GEMM (4q x 4d tiles, k-split 2).
__global__ __launch_bounds__(256) void attn_kernel(const float* __restrict__ qkv2,
                                                   float* __restrict__ out)
{
    extern __shared__ float sm[];
    float* Qt   = sm;                       // 32*QT_S
    float* Kt   = Qt + 32 * QT_S;           // 32*KT_S
    float* Vs   = Kt + 32 * KT_S;           // 128*V_S
    float* Pt   = Vs + 128 * V_S;           // 128*PT_S (also Qraw/Obuf)
    float* l_sm = Pt + 128 * PT_S;          // 64
    float* tab  = l_sm + 64;                // 529

    int widx = blockIdx.x, h = blockIdx.y;
    int b  = widx >> 8;
    int wr = (widx >> 4) & 15;
    int wc = widx & 15;
    int tid  = threadIdx.x;
    int lane = tid & 31;

    for (int t = tid; t < 529; t += 256) tab[t] = g_bias_tab[h * 529 + t];

    // ---- Q prep: cooperative load into Qraw, normalize+scale into Qt (transposed)
    float* Qraw = Pt;
    for (int t = tid; t < 512; t += 256) {
        int q = t >> 3, d4 = (t & 7) << 2;
        int pr = wr * 8 + (q >> 3), pc = wc * 8 + (q & 7);
        const float* p = qkv2 + ((size_t)((b * 128 + pr) * 128 + pc)) * C3 + h * HD + d4;
        *reinterpret_cast<float4*>(&Qraw[q * QR_S + d4]) = *reinterpret_cast<const float4*>(p);
    }
    __syncthreads();
    if (tid < 64) {
        float v[32]; float ss = 0.f;
#pragma unroll
        for (int d = 0; d < 32; d++) { v[d] = Qraw[tid * QR_S + d]; ss = fmaf(v[d], v[d], ss); }
        float qmul = rsqrtf(fmaxf(ss, 1.55e-5f)) * g_scale[h];
#pragma unroll
        for (int d = 0; d < 32; d++) Qt[d * QT_S + tid] = v[d] * qmul;
    }

    // role mappings
    int mS = tid >> 5, n = tid & 31;                        // S-GEMM
    int dg = tid & 7, m4 = (tid >> 3) & 15, ks = tid >> 7;  // PV-GEMM

    float oacc[4][4];
#pragma unroll
    for (int i = 0; i < 4; i++)
#pragma unroll
        for (int j = 0; j < 4; j++) oacc[i][j] = 0.f;

    for (int half = 0; half < 2; half++) {
        __syncthreads();  // Qt ready / previous Pt,K,V consumers done

        // ---- load K/V half tile (zero-padded halo); K stored transposed
        int base_r = wr * 8 - 4 + 8 * half, base_c = wc * 8 - 4;
        for (int i = tid; i < 128 * 8; i += 256) {
            int kl = i >> 3, d4 = (i & 7) << 2;
            int gr = base_r + (kl >> 4), gc = base_c + (kl & 15);
            float4 k4 = make_float4(0.f, 0.f, 0.f, 0.f);
            float4 v4 = make_float4(0.f, 0.f, 0.f, 0.f);
            if (gr >= 0 && gr < 128 && gc >= 0 && gc < 128) {
                const float* p = qkv2 + ((size_t)((b * 128 + gr) * 128 + gc)) * C3 + Cc + h * HD + d4;
                k4 = *reinterpret_cast<const float4*>(p);
                v4 = *reinterpret_cast<const float4*>(p + Cc);
            }
            Kt[(d4 + 0) * KT_S + kl] = k4.x;
            Kt[(d4 + 1) * KT_S + kl] = k4.y;
            Kt[(d4 + 2) * KT_S + kl] = k4.z;
            Kt[(d4 + 3) * KT_S + kl] = k4.w;
            *reinterpret_cast<float4*>(&Vs[kl * V_S + d4]) = v4;
        }
        __syncthreads();

        // ---- normalize K columns
        if (tid < 128) {
            float r[32]; float ss = 0.f;
#pragma unroll
            for (int d = 0; d < 32; d++) { r[d] = Kt[d * KT_S + tid]; ss = fmaf(r[d], r[d], ss); }
            float rs = rsqrtf(fmaxf(ss, 1.55e-5f));
#pragma unroll
            for (int d = 0; d < 32; d++) Kt[d * KT_S + tid] = r[d] * rs;
        }
        __syncthreads();

        // ---- S GEMM: acc[8][4] over 32 dims
        float acc[8][4];
#pragma unroll
        for (int i = 0; i < 8; i++)
#pragma unroll
            for (int j = 0; j < 4; j++) acc[i][j] = 0.f;

#pragma unroll 8
        for (int kk = 0; kk < 32; kk++) {
            float qv[8];
            *reinterpret_cast<float4*>(&qv[0]) = *reinterpret_cast<const float4*>(&Qt[kk * QT_S + mS * 8]);
            *reinterpret_cast<float4*>(&qv[4]) = *reinterpret_cast<const float4*>(&Qt[kk * QT_S + mS * 8 + 4]);
            float kv[4];
#pragma unroll
            for (int j = 0; j < 4; j++) kv[j] = Kt[kk * KT_S + n + 32 * j];
#pragma unroll
            for (int i = 0; i < 8; i++)
#pragma unroll
                for (int j = 0; j < 4; j++)
                    acc[i][j] = fmaf(qv[i], kv[j], acc[i][j]);
        }

        // ---- bias + exp + rowsums + store P transposed
        float rowp[8];
#pragma unroll
        for (int i = 0; i < 8; i++) rowp[i] = 0.f;
#pragma unroll
        for (int j = 0; j < 4; j++) {
            int kl = n + 32 * j;
            int kr = (kl >> 4) + 8 * half, kc = kl & 15;
            int basei = (mS - kr + 15) * 23 + 15 - kc;
#pragma unroll
            for (int i = 0; i < 8; i++) {
                float p = __expf(acc[i][j] + tab[basei + i] - 16.0f);
                rowp[i] += p;
                Pt[kl * PT_S + mS * 8 + i] = p;
            }
        }
#pragma unroll
        for (int i = 0; i < 8; i++) {
            float s = rowp[i];
#pragma unroll
            for (int off = 16; off > 0; off >>= 1)
                s += __shfl_xor_sync(0xffffffffu, s, off);
            if (lane == 0) {
                int q = mS * 8 + i;
                l_sm[q] = half ? (l_sm[q] + s) : s;
            }
        }
        __syncthreads();

        // ---- PV GEMM: oacc[4q][4d] += P^T V (k-split 2)
        int kbase = ks * 64;
#pragma unroll 8
        for (int kk = 0; kk < 64; kk++) {
            int kl = kbase + kk;
            float4 v4 = *reinterpret_cast<const float4*>(&Vs[kl * V_S + dg * 4]);
            float pv[4];
#pragma unroll
            for (int i = 0; i < 4; i++) pv[i] = Pt[kl * PT_S + m4 * 4 + i];
#pragma unroll
            for (int i = 0; i < 4; i++) {
                oacc[i][0] = fmaf(pv[i], v4.x, oacc[i][0]);
                oacc[i][1] = fmaf(pv[i], v4.y, oacc[i][1]);
                oacc[i][2] = fmaf(pv[i], v4.z, oacc[i][2]);
                oacc[i][3] = fmaf(pv[i], v4.w, oacc[i][3]);
            }
        }
    }

    // ---- merge k-split partials and write out
    __syncthreads();
    float* Obuf = Pt;
    if (ks == 1) {
#pragma unroll
        for (int i = 0; i < 4; i++)
            *reinterpret_cast<float4*>(&Obuf[(m4 * 4 + i) * QR_S + dg * 4]) =
                make_float4(oacc[i][0], oacc[i][1], oacc[i][2], oacc[i][3]);
    }
    __syncthreads();
    if (ks == 0) {
#pragma unroll
        for (int i = 0; i < 4; i++) {
            int q = m4 * 4 + i;
            float4 w = *reinterpret_cast<const float4*>(&Obuf[q * QR_S + dg * 4]);
            float linv = 1.0f / l_sm[q];
            int pr = wr * 8 + (q >> 3), pc = wc * 8 + (q & 7);
            float* op = out + ((size_t)((b * 128 + pr) * 128 + pc)) * Cc + h * HD + dg * 4;
            *reinterpret_cast<float4*>(op) =
                make_float4((oacc[i][0] + w.x) * linv, (oacc[i][1] + w.y) * linv,
                            (oacc[i][2] + w.z) * linv, (oacc[i][3] + w.w) * linv);
        }
    }
}

// ---------------- launch ----------------
extern "C" void kernel_launch(void* const* d_in, const int* in_sizes, int n_in,
                              void* d_out, int out_size)
{
    const float* x           = (const float*)d_in[0];
    const float* w_qkv       = (const float*)d_in[1];
    const float* w_dw        = (const float*)d_in[2];
    const float* ln_g        = (const float*)d_in[3];
    const float* ln_b        = (const float*)d_in[4];
    const float* q_bias      = (const float*)d_in[5];
    const float* v_bias      = (const float*)d_in[6];
    const float* logit_scale = (const float*)d_in[7];
    const float* cpb_w1      = (const float*)d_in[8];
    const float* cpb_b1      = (const float*)d_in[9];
    const float* cpb_w2      = (const float*)d_in[10];
    const float* w_proj      = (const float*)d_in[11];
    float* out = (float*)d_out;

    float *p_qkv, *p_qkv2, *p_att;
    cudaGetSymbolAddress((void**)&p_qkv,  g_qkv);
    cudaGetSymbolAddress((void**)&p_qkv2, g_qkv2);
    cudaGetSymbolAddress((void**)&p_att,  g_att);

    const int ATTN_SMEM = (32 * QT_S + 32 * KT_S + 128 * V_S + 128 * PT_S + 64 + 529) * 4;
    cudaFuncSetAttribute(attn_kernel, cudaFuncAttributeMaxDynamicSharedMemorySize, ATTN_SMEM);

    // 1) CPB bias table + per-head scales (tiny)
    cpb_kernel<<<5, 128>>>(cpb_w1, cpb_b1, cpb_w2, logit_scale);

    // 2) qkv = x @ w_qkv   [32768 x 256] @ [256 x 768]
    sgemm128<<<dim3(C3 / 128, NPIX / 128), 256>>>(x, w_qkv, p_qkv, NPIX, C3, Cc);

    // 3) depthwise conv + LN + bias
    convln_kernel<<<NPIX, 256>>>(p_qkv, w_dw, ln_g, ln_b, q_bias, v_bias, p_qkv2);

    // 4) fused windowed attention
    attn_kernel<<<dim3(NWIN, HEADS), 256, ATTN_SMEM>>>(p_qkv2, p_att);

    // 5) out = att @ w_proj   [32768 x 256] @ [256 x 256]
    sgemm128<<<dim3(Cc / 128, NPIX / 128), 256>>>(p_att, w_proj, out, NPIX, Cc, Cc);
}

// round 13
// speedup vs baseline: 1.8269x; 1.4244x over previous
#include <cuda_runtime.h>
#include <cstdint>
#include <cstddef>

#define Bc 2
#define Hc 128
#define Wc 128
#define Cc 256
#define C3 768
#define NPIX (Bc*Hc*Wc)           // 32768
#define HEADS 8
#define HD 32
#define WS 8
#define KW 16
#define NWIN 512                  // B * 16 * 16
#define GK 256                    // GEMM K (both GEMMs)

// attention smem strides (floats) chosen for bank-conflict-free access
#define QT_S 72
#define KT_S 133
#define V_S  40
#define PT_S 65
#define QR_S 36

// tgemm smem: [128 rows][36 floats] per operand per stage
#define TS_ROW 36
#define TG_STAGE_F (2 * 128 * TS_ROW)          // floats per stage (A+B)
#define TG_SMEM_B  (2 * TG_STAGE_F * 4)        // 73728 bytes

// ---------------- scratch (device globals; no allocation) ----------------
__device__ __align__(16) float g_qkv [(size_t)NPIX * C3];
__device__ __align__(16) float g_qkv2[(size_t)NPIX * C3];
__device__ __align__(16) float g_att [(size_t)NPIX * Cc];
__device__ __align__(16) float g_wqkvT[(size_t)C3 * Cc];   // w_qkv^T [768][256]
__device__ __align__(16) float g_wprojT[(size_t)Cc * Cc];  // w_proj^T [256][256]
__device__ __align__(16) float g_bias_tab[8 * 529];
__device__ float g_scale[8];

// ---------------- helpers ----------------
__device__ __forceinline__ uint32_t smem_u32(const void* p) {
    uint32_t a;
    asm("{ .reg .u64 t; cvta.to.shared.u64 t, %1; cvt.u32.u64 %0, t; }" : "=r"(a) : "l"(p));
    return a;
}
__device__ __forceinline__ uint32_t to_tf32(float f) {
    uint32_t r;
    asm("cvt.rna.tf32.f32 %0, %1;" : "=r"(r) : "f"(f));
    return r;
}
#define CP_ASYNC16(dst, src) asm volatile("cp.async.cg.shared.global [%0], [%1], 16;" :: "r"(dst), "l"(src) : "memory")
#define CP_COMMIT()          asm volatile("cp.async.commit_group;" ::: "memory")
#define CP_WAIT(n)           asm volatile("cp.async.wait_group %0;" :: "n"(n) : "memory")

// ---------------- weight transpose (tiny) ----------------
__global__ void transpose_kernel(const float* __restrict__ W, float* __restrict__ WT,
                                 int K, int N)
{
    int i = blockIdx.x * 256 + threadIdx.x;
    if (i >= K * N) return;
    int k = i / N, n = i % N;
    WT[(size_t)n * K + k] = W[i];
}

// ---------------- mma.sync tf32 GEMM: C[M,N] = A[M,GK] * Bt[N,GK]^T ----------------
// grid (N/128, M/128), 256 threads = 8 warps (2x4), warp tile 64x32, m16n8k8.
__global__ __launch_bounds__(256, 2) void tgemm(const float* __restrict__ A,
                                                const float* __restrict__ Bt,
                                                float* __restrict__ C, int N)
{
    extern __shared__ float sm[];
    uint32_t sb = smem_u32(sm);

    int tid  = threadIdx.x;
    int wid  = tid >> 5, lane = tid & 31;
    int gid  = lane >> 2, tg = lane & 3;
    int wr   = wid >> 2, wcol = wid & 3;
    int bx = blockIdx.x, by = blockIdx.y;

    const float* Ab = A  + (size_t)(by * 128) * GK;
    const float* Bb = Bt + (size_t)(bx * 128) * GK;

    float c[4][4][4];
#pragma unroll
    for (int mt = 0; mt < 4; mt++)
#pragma unroll
        for (int nt = 0; nt < 4; nt++)
#pragma unroll
            for (int i = 0; i < 4; i++) c[mt][nt][i] = 0.f;

    int ld_row = tid >> 3, ld_c4 = tid & 7;   // base mapping; rows advance by 32/iter

    // issue one 32-K chunk (A+B) into stage kt&1 via cp.async
#define TG_ISSUE(kt) do { \
        int _bs = (kt) & 1; \
        uint32_t _ab = sb + _bs * (TG_STAGE_F * 4); \
        uint32_t _bbx = _ab + 128 * TS_ROW * 4; \
        const float* _ga = Ab + (kt) * 32; \
        const float* _gb = Bb + (kt) * 32; \
        _Pragma("unroll") \
        for (int _it = 0; _it < 4; _it++) { \
            int _row = ld_row + _it * 32; \
            uint32_t _off = (_row * TS_ROW + ld_c4 * 4) * 4; \
            CP_ASYNC16(_ab  + _off, _ga + (size_t)_row * GK + ld_c4 * 4); \
            CP_ASYNC16(_bbx + _off, _gb + (size_t)_row * GK + ld_c4 * 4); \
        } \
        CP_COMMIT(); \
    } while (0)

    TG_ISSUE(0);

    for (int kt = 0; kt < 8; kt++) {
        if (kt + 1 < 8) { TG_ISSUE(kt + 1); CP_WAIT(1); }
        else            { CP_WAIT(0); }
        __syncthreads();

        const float* Asb = sm + (kt & 1) * TG_STAGE_F;
        const float* Bsb = Asb + 128 * TS_ROW;

#pragma unroll
        for (int kk = 0; kk < 32; kk += 8) {
            uint32_t a[4][4], b[4][2];
#pragma unroll
            for (int mt = 0; mt < 4; mt++) {
                const float* ar = Asb + (wr * 64 + mt * 16 + gid) * TS_ROW + kk + tg;
                a[mt][0] = to_tf32(ar[0]);
                a[mt][1] = to_tf32(ar[8 * TS_ROW]);
                a[mt][2] = to_tf32(ar[4]);
                a[mt][3] = to_tf32(ar[8 * TS_ROW + 4]);
            }
#pragma unroll
            for (int nt = 0; nt < 4; nt++) {
                const float* br = Bsb + (wcol * 32 + nt * 8 + gid) * TS_ROW + kk + tg;
                b[nt][0] = to_tf32(br[0]);
                b[nt][1] = to_tf32(br[4]);
            }
#pragma unroll
            for (int mt = 0; mt < 4; mt++)
#pragma unroll
                for (int nt = 0; nt < 4; nt++)
                    asm volatile(
                        "mma.sync.aligned.m16n8k8.row.col.f32.tf32.tf32.f32 "
                        "{%0,%1,%2,%3}, {%4,%5,%6,%7}, {%8,%9}, {%0,%1,%2,%3};"
                        : "+f"(c[mt][nt][0]), "+f"(c[mt][nt][1]),
                          "+f"(c[mt][nt][2]), "+f"(c[mt][nt][3])
                        : "r"(a[mt][0]), "r"(a[mt][1]), "r"(a[mt][2]), "r"(a[mt][3]),
                          "r"(b[nt][0]), "r"(b[nt][1]));
        }
        __syncthreads();
    }

#pragma unroll
    for (int mt = 0; mt < 4; mt++) {
        int row = by * 128 + wr * 64 + mt * 16 + gid;
#pragma unroll
        for (int nt = 0; nt < 4; nt++) {
            int col = bx * 128 + wcol * 32 + nt * 8 + 2 * tg;
            *reinterpret_cast<float2*>(&C[(size_t)row * N + col]) =
                make_float2(c[mt][nt][0], c[mt][nt][1]);
            *reinterpret_cast<float2*>(&C[(size_t)(row + 8) * N + col]) =
                make_float2(c[mt][nt][2], c[mt][nt][3]);
        }
    }
#undef TG_ISSUE
}

// ---------------- CPB MLP + per-head scale ----------------
__global__ void cpb_kernel(const float* __restrict__ w1, const float* __restrict__ b1,
                           const float* __restrict__ w2, const float* __restrict__ ls)
{
    int t = blockIdx.x * blockDim.x + threadIdx.x;
    if (t < 8) g_scale[t] = expf(fminf(ls[t], 4.605170185988091f)); // log(100)
    if (t >= 529) return;
    int a = t / 23, b = t % 23;
    float c0 = (float)(a - 11) * (8.0f / 7.0f);
    float c1 = (float)(b - 11) * (8.0f / 7.0f);
    const float inv_log8 = 0.4808983469629878f;
    float v0 = copysignf(log1pf(fabsf(c0)), c0) * inv_log8;
    float v1 = copysignf(log1pf(fabsf(c1)), c1) * inv_log8;
    float acc[8];
#pragma unroll
    for (int h = 0; h < 8; h++) acc[h] = 0.f;
    for (int j = 0; j < 512; j++) {
        float hv = fmaxf(fmaf(v0, w1[j], fmaf(v1, w1[512 + j], b1[j])), 0.f);
#pragma unroll
        for (int h = 0; h < 8; h++) acc[h] += hv * w2[j * 8 + h];
    }
#pragma unroll
    for (int h = 0; h < 8; h++)
        g_bias_tab[h * 529 + t] = 16.0f / (1.0f + expf(-acc[h]));
}

// ---------------- depthwise 3x3 conv + LayerNorm + qkv bias (fused) ----------------
__global__ __launch_bounds__(256) void convln_kernel(const float* __restrict__ qkv,
                                                     const float* __restrict__ wdw,
                                                     const float* __restrict__ lng,
                                                     const float* __restrict__ lnb,
                                                     const float* __restrict__ qb,
                                                     const float* __restrict__ vb,
                                                     float* __restrict__ out)
{
    int p  = blockIdx.x;
    int b  = p >> 14;
    int hh = (p >> 7) & 127;
    int ww = p & 127;
    int tid = threadIdx.x;

    float acc[3];
#pragma unroll
    for (int cc = 0; cc < 3; cc++) {
        int c = tid + cc * 256;
        float a = 0.f;
#pragma unroll
        for (int dh = -1; dh <= 1; dh++) {
            int rr = hh + dh;
            if (rr < 0 || rr > 127) continue;
#pragma unroll
            for (int dw = -1; dw <= 1; dw++) {
                int col = ww + dw;
                if (col < 0 || col > 127) continue;
                a = fmaf(qkv[((size_t)((b * 128 + rr) * 128 + col)) * C3 + c],
                         wdw[((dh + 1) * 3 + (dw + 1)) * C3 + c], a);
            }
        }
        acc[cc] = a;
    }
    float s  = acc[0] + acc[1] + acc[2];
    float sq = acc[0] * acc[0] + acc[1] * acc[1] + acc[2] * acc[2];
#pragma unroll
    for (int off = 16; off > 0; off >>= 1) {
        s  += __shfl_xor_sync(0xffffffffu, s,  off);
        sq += __shfl_xor_sync(0xffffffffu, sq, off);
    }
    __shared__ float reds[8], redq[8];
    int wid = tid >> 5, lane = tid & 31;
    if (lane == 0) { reds[wid] = s; redq[wid] = sq; }
    __syncthreads();
    float st = 0.f, sqt = 0.f;
#pragma unroll
    for (int i = 0; i < 8; i++) { st += reds[i]; sqt += redq[i]; }
    float mu   = st * (1.0f / 768.0f);
    float var  = sqt * (1.0f / 768.0f) - mu * mu;
    float rstd = rsqrtf(var + 1e-5f);

    size_t base = (size_t)p * C3;
#pragma unroll
    for (int cc = 0; cc < 3; cc++) {
        int c = tid + cc * 256;
        float y = (acc[cc] - mu) * rstd * lng[c] + lnb[c];
        if (c < 256)       y += qb[c];
        else if (c >= 512) y += vb[c - 512];
        out[base + c] = y;
    }
}

// ---------------- fused windowed cosine attention (register-tiled GEMMs) ----------------
__global__ __launch_bounds__(256) void attn_kernel(const float* __restrict__ qkv2,
                                                   float* __restrict__ out)
{
    extern __shared__ float sm[];
    float* Qt   = sm;
    float* Kt   = Qt + 32 * QT_S;
    float* Vs   = Kt + 32 * KT_S;
    float* Pt   = Vs + 128 * V_S;
    float* l_sm = Pt + 128 * PT_S;
    float* tab  = l_sm + 64;

    int widx = blockIdx.x, h = blockIdx.y;
    int b  = widx >> 8;
    int wr = (widx >> 4) & 15;
    int wc = widx & 15;
    int tid  = threadIdx.x;
    int lane = tid & 31;

    for (int t = tid; t < 529; t += 256) tab[t] = g_bias_tab[h * 529 + t];

    float* Qraw = Pt;
    for (int t = tid; t < 512; t += 256) {
        int q = t >> 3, d4 = (t & 7) << 2;
        int pr = wr * 8 + (q >> 3), pc = wc * 8 + (q & 7);
        const float* p = qkv2 + ((size_t)((b * 128 + pr) * 128 + pc)) * C3 + h * HD + d4;
        *reinterpret_cast<float4*>(&Qraw[q * QR_S + d4]) = *reinterpret_cast<const float4*>(p);
    }
    __syncthreads();
    if (tid < 64) {
        float v[32]; float ss = 0.f;
#pragma unroll
        for (int d = 0; d < 32; d++) { v[d] = Qraw[tid * QR_S + d]; ss = fmaf(v[d], v[d], ss); }
        float qmul = rsqrtf(fmaxf(ss, 1.55e-5f)) * g_scale[h];
#pragma unroll
        for (int d = 0; d < 32; d++) Qt[d * QT_S + tid] = v[d] * qmul;
    }

    int mS = tid >> 5, n = tid & 31;
    int dg = tid & 7, m4 = (tid >> 3) & 15, ks = tid >> 7;

    float oacc[4][4];
#pragma unroll
    for (int i = 0; i < 4; i++)
#pragma unroll
        for (int j = 0; j < 4; j++) oacc[i][j] = 0.f;

    for (int half = 0; half < 2; half++) {
        __syncthreads();

        int base_r = wr * 8 - 4 + 8 * half, base_c = wc * 8 - 4;
        for (int i = tid; i < 128 * 8; i += 256) {
            int kl = i >> 3, d4 = (i & 7) << 2;
            int gr = base_r + (kl >> 4), gc = base_c + (kl & 15);
            float4 k4 = make_float4(0.f, 0.f, 0.f, 0.f);
            float4 v4 = make_float4(0.f, 0.f, 0.f, 0.f);
            if (gr >= 0 && gr < 128 && gc >= 0 && gc < 128) {
                const float* p = qkv2 + ((size_t)((b * 128 + gr) * 128 + gc)) * C3 + Cc + h * HD + d4;
                k4 = *reinterpret_cast<const float4*>(p);
                v4 = *reinterpret_cast<const float4*>(p + Cc);
            }
            Kt[(d4 + 0) * KT_S + kl] = k4.x;
            Kt[(d4 + 1) * KT_S + kl] = k4.y;
            Kt[(d4 + 2) * KT_S + kl] = k4.z;
            Kt[(d4 + 3) * KT_S + kl] = k4.w;
            *reinterpret_cast<float4*>(&Vs[kl * V_S + d4]) = v4;
        }
        __syncthreads();

        if (tid < 128) {
            float r[32]; float ss = 0.f;
#pragma unroll
            for (int d = 0; d < 32; d++) { r[d] = Kt[d * KT_S + tid]; ss = fmaf(r[d], r[d], ss); }
            float rs = rsqrtf(fmaxf(ss, 1.55e-5f));
#pragma unroll
            for (int d = 0; d < 32; d++) Kt[d * KT_S + tid] = r[d] * rs;
        }
        __syncthreads();

        float acc[8][4];
#pragma unroll
        for (int i = 0; i < 8; i++)
#pragma unroll
            for (int j = 0; j < 4; j++) acc[i][j] = 0.f;

#pragma unroll 8
        for (int kk = 0; kk < 32; kk++) {
            float qv[8];
            *reinterpret_cast<float4*>(&qv[0]) = *reinterpret_cast<const float4*>(&Qt[kk * QT_S + mS * 8]);
            *reinterpret_cast<float4*>(&qv[4]) = *reinterpret_cast<const float4*>(&Qt[kk * QT_S + mS * 8 + 4]);
            float kv[4];
#pragma unroll
            for (int j = 0; j < 4; j++) kv[j] = Kt[kk * KT_S + n + 32 * j];
#pragma unroll
            for (int i = 0; i < 8; i++)
#pragma unroll
                for (int j = 0; j < 4; j++)
                    acc[i][j] = fmaf(qv[i], kv[j], acc[i][j]);
        }

        float rowp[8];
#pragma unroll
        for (int i = 0; i < 8; i++) rowp[i] = 0.f;
#pragma unroll
        for (int j = 0; j < 4; j++) {
            int kl = n + 32 * j;
            int kr = (kl >> 4) + 8 * half, kc = kl & 15;
            int basei = (mS - kr + 15) * 23 + 15 - kc;
#pragma unroll
            for (int i = 0; i < 8; i++) {
                float p = __expf(acc[i][j] + tab[basei + i] - 16.0f);
                rowp[i] += p;
                Pt[kl * PT_S + mS * 8 + i] = p;
            }
        }
#pragma unroll
        for (int i = 0; i < 8; i++) {
            float s = rowp[i];
#pragma unroll
            for (int off = 16; off > 0; off >>= 1)
                s += __shfl_xor_sync(0xffffffffu, s, off);
            if (lane == 0) {
                int q = mS * 8 + i;
                l_sm[q] = half ? (l_sm[q] + s) : s;
            }
        }
        __syncthreads();

        int kbase = ks * 64;
#pragma unroll 8
        for (int kk = 0; kk < 64; kk++) {
            int kl = kbase + kk;
            float4 v4 = *reinterpret_cast<const float4*>(&Vs[kl * V_S + dg * 4]);
            float pv[4];
#pragma unroll
            for (int i = 0; i < 4; i++) pv[i] = Pt[kl * PT_S + m4 * 4 + i];
#pragma unroll
            for (int i = 0; i < 4; i++) {
                oacc[i][0] = fmaf(pv[i], v4.x, oacc[i][0]);
                oacc[i][1] = fmaf(pv[i], v4.y, oacc[i][1]);
                oacc[i][2] = fmaf(pv[i], v4.z, oacc[i][2]);
                oacc[i][3] = fmaf(pv[i], v4.w, oacc[i][3]);
            }
        }
    }

    __syncthreads();
    float* Obuf = Pt;
    if (ks == 1) {
#pragma unroll
        for (int i = 0; i < 4; i++)
            *reinterpret_cast<float4*>(&Obuf[(m4 * 4 + i) * QR_S + dg * 4]) =
                make_float4(oacc[i][0], oacc[i][1], oacc[i][2], oacc[i][3]);
    }
    __syncthreads();
    if (ks == 0) {
#pragma unroll
        for (int i = 0; i < 4; i++) {
            int q = m4 * 4 + i;
            float4 w = *reinterpret_cast<const float4*>(&Obuf[q * QR_S + dg * 4]);
            float linv = 1.0f / l_sm[q];
            int pr = wr * 8 + (q >> 3), pc = wc * 8 + (q & 7);
            float* op = out + ((size_t)((b * 128 + pr) * 128 + pc)) * Cc + h * HD + dg * 4;
            *reinterpret_cast<float4*>(op) =
                make_float4((oacc[i][0] + w.x) * linv, (oacc[i][1] + w.y) * linv,
                            (oacc[i][2] + w.z) * linv, (oacc[i][3] + w.w) * linv);
        }
    }
}

// ---------------- launch ----------------
extern "C" void kernel_launch(void* const* d_in, const int* in_sizes, int n_in,
                              void* d_out, int out_size)
{
    const float* x           = (const float*)d_in[0];
    const float* w_qkv       = (const float*)d_in[1];
    const float* w_dw        = (const float*)d_in[2];
    const float* ln_g        = (const float*)d_in[3];
    const float* ln_b        = (const float*)d_in[4];
    const float* q_bias      = (const float*)d_in[5];
    const float* v_bias      = (const float*)d_in[6];
    const float* logit_scale = (const float*)d_in[7];
    const float* cpb_w1      = (const float*)d_in[8];
    const float* cpb_b1      = (const float*)d_in[9];
    const float* cpb_w2      = (const float*)d_in[10];
    const float* w_proj      = (const float*)d_in[11];
    float* out = (float*)d_out;

    float *p_qkv, *p_qkv2, *p_att, *p_wqkvT, *p_wprojT;
    cudaGetSymbolAddress((void**)&p_qkv,   g_qkv);
    cudaGetSymbolAddress((void**)&p_qkv2,  g_qkv2);
    cudaGetSymbolAddress((void**)&p_att,   g_att);
    cudaGetSymbolAddress((void**)&p_wqkvT, g_wqkvT);
    cudaGetSymbolAddress((void**)&p_wprojT,g_wprojT);

    const int ATTN_SMEM = (32 * QT_S + 32 * KT_S + 128 * V_S + 128 * PT_S + 64 + 529) * 4;
    cudaFuncSetAttribute(attn_kernel, cudaFuncAttributeMaxDynamicSharedMemorySize, ATTN_SMEM);
    cudaFuncSetAttribute(tgemm, cudaFuncAttributeMaxDynamicSharedMemorySize, TG_SMEM_B);

    // 0) transpose weights to [N][K] K-major
    transpose_kernel<<<(Cc * C3 + 255) / 256, 256>>>(w_qkv, p_wqkvT, Cc, C3);
    transpose_kernel<<<(Cc * Cc + 255) / 256, 256>>>(w_proj, p_wprojT, Cc, Cc);

    // 1) CPB bias table + per-head scales
    cpb_kernel<<<5, 128>>>(cpb_w1, cpb_b1, cpb_w2, logit_scale);

    // 2) qkv = x @ w_qkv  (mma.sync tf32)  [32768 x 256] @ [256 x 768]
    tgemm<<<dim3(C3 / 128, NPIX / 128), 256, TG_SMEM_B>>>(x, p_wqkvT, p_qkv, C3);

    // 3) depthwise conv + LN + bias
    convln_kernel<<<NPIX, 256>>>(p_qkv, w_dw, ln_g, ln_b, q_bias, v_bias, p_qkv2);

    // 4) fused windowed attention
    attn_kernel<<<dim3(NWIN, HEADS), 256, ATTN_SMEM>>>(p_qkv2, p_att);

    // 5) out = att @ w_proj  (mma.sync tf32)  [32768 x 256] @ [256 x 256]
    tgemm<<<dim3(Cc / 128, NPIX / 128), 256, TG_SMEM_B>>>(p_att, p_wprojT, out, Cc);
}

// round 14
// speedup vs baseline: 1.9800x; 1.0838x over previous
#include <cuda_runtime.h>
#include <cstdint>
#include <cstddef>

#define Bc 2
#define Hc 128
#define Wc 128
#define Cc 256
#define C3 768
#define NPIX (Bc*Hc*Wc)           // 32768
#define HEADS 8
#define HD 32
#define WS 8
#define KW 16
#define NWIN 512                  // B * 16 * 16
#define GK 256                    // GEMM K (both GEMMs)

// tgemm smem: [128 rows][36 floats] per operand per stage
#define TS_ROW 36
#define TG_STAGE_F (2 * 128 * TS_ROW)          // floats per stage (A+B)
#define TG_SMEM_B  (2 * TG_STAGE_F * 4)        // 73728 bytes

// attn smem strides (floats): bank = 4*gid+tg = lane -> conflict-free frag loads
#define QN_S 36    // Qn[64][36]
#define KN_S 36    // Kn[128][36]
#define V_S  40    // Vs[128][40]  (PV B-frag: bank = 8*tg+gid, conflict-free)
#define P_S  132   // Pt[64][132]  (132 mod 32 = 4 -> conflict-free A-frag)

// ---------------- scratch (device globals; no allocation) ----------------
__device__ __align__(16) float g_qkv [(size_t)NPIX * C3];
__device__ __align__(16) float g_qkv2[(size_t)NPIX * C3];
__device__ __align__(16) float g_att [(size_t)NPIX * Cc];
__device__ __align__(16) float g_wqkvT[(size_t)C3 * Cc];   // w_qkv^T [768][256]
__device__ __align__(16) float g_wprojT[(size_t)Cc * Cc];  // w_proj^T [256][256]
__device__ __align__(16) float g_bias_tab[8 * 529];
__device__ float g_scale[8];

// ---------------- helpers ----------------
__device__ __forceinline__ uint32_t smem_u32(const void* p) {
    uint32_t a;
    asm("{ .reg .u64 t; cvta.to.shared.u64 t, %1; cvt.u32.u64 %0, t; }" : "=r"(a) : "l"(p));
    return a;
}
__device__ __forceinline__ uint32_t to_tf32(float f) {
    uint32_t r;
    asm("cvt.rna.tf32.f32 %0, %1;" : "=r"(r) : "f"(f));
    return r;
}
// split f into tf32 hi + tf32 lo (error-compensation pair)
__device__ __forceinline__ void tf32_split(float f, uint32_t& hi, uint32_t& lo) {
    hi = to_tf32(f);
    lo = to_tf32(f - __uint_as_float(hi));
}
#define MMA_TF32(c, a0,a1,a2,a3, b0,b1) \
    asm volatile("mma.sync.aligned.m16n8k8.row.col.f32.tf32.tf32.f32 " \
        "{%0,%1,%2,%3}, {%4,%5,%6,%7}, {%8,%9}, {%0,%1,%2,%3};" \
        : "+f"((c)[0]), "+f"((c)[1]), "+f"((c)[2]), "+f"((c)[3]) \
        : "r"(a0), "r"(a1), "r"(a2), "r"(a3), "r"(b0), "r"(b1))

#define CP_ASYNC16(dst, src) asm volatile("cp.async.cg.shared.global [%0], [%1], 16;" :: "r"(dst), "l"(src) : "memory")
#define CP_COMMIT()          asm volatile("cp.async.commit_group;" ::: "memory")
#define CP_WAIT(n)           asm volatile("cp.async.wait_group %0;" :: "n"(n) : "memory")

// ---------------- weight transpose (tiny) ----------------
__global__ void transpose_kernel(const float* __restrict__ W, float* __restrict__ WT,
                                 int K, int N)
{
    int i = blockIdx.x * 256 + threadIdx.x;
    if (i >= K * N) return;
    int k = i / N, n = i % N;
    WT[(size_t)n * K + k] = W[i];
}

// ---------------- mma.sync tf32 GEMM: C[M,N] = A[M,GK] * Bt[N,GK]^T ----------------
__global__ __launch_bounds__(256, 2) void tgemm(const float* __restrict__ A,
                                                const float* __restrict__ Bt,
                                                float* __restrict__ C, int N)
{
    extern __shared__ float sm[];
    uint32_t sb = smem_u32(sm);

    int tid  = threadIdx.x;
    int wid  = tid >> 5, lane = tid & 31;
    int gid  = lane >> 2, tg = lane & 3;
    int wr   = wid >> 2, wcol = wid & 3;
    int bx = blockIdx.x, by = blockIdx.y;

    const float* Ab = A  + (size_t)(by * 128) * GK;
    const float* Bb = Bt + (size_t)(bx * 128) * GK;

    float c[4][4][4];
#pragma unroll
    for (int mt = 0; mt < 4; mt++)
#pragma unroll
        for (int nt = 0; nt < 4; nt++)
#pragma unroll
            for (int i = 0; i < 4; i++) c[mt][nt][i] = 0.f;

    int ld_row = tid >> 3, ld_c4 = tid & 7;

#define TG_ISSUE(kt) do { \
        int _bs = (kt) & 1; \
        uint32_t _ab = sb + _bs * (TG_STAGE_F * 4); \
        uint32_t _bbx = _ab + 128 * TS_ROW * 4; \
        const float* _ga = Ab + (kt) * 32; \
        const float* _gb = Bb + (kt) * 32; \
        _Pragma("unroll") \
        for (int _it = 0; _it < 4; _it++) { \
            int _row = ld_row + _it * 32; \
            uint32_t _off = (_row * TS_ROW + ld_c4 * 4) * 4; \
            CP_ASYNC16(_ab  + _off, _ga + (size_t)_row * GK + ld_c4 * 4); \
            CP_ASYNC16(_bbx + _off, _gb + (size_t)_row * GK + ld_c4 * 4); \
        } \
        CP_COMMIT(); \
    } while (0)

    TG_ISSUE(0);

    for (int kt = 0; kt < 8; kt++) {
        if (kt + 1 < 8) { TG_ISSUE(kt + 1); CP_WAIT(1); }
        else            { CP_WAIT(0); }
        __syncthreads();

        const float* Asb = sm + (kt & 1) * TG_STAGE_F;
        const float* Bsb = Asb + 128 * TS_ROW;

#pragma unroll
        for (int kk = 0; kk < 32; kk += 8) {
            uint32_t a[4][4], b[4][2];
#pragma unroll
            for (int mt = 0; mt < 4; mt++) {
                const float* ar = Asb + (wr * 64 + mt * 16 + gid) * TS_ROW + kk + tg;
                a[mt][0] = to_tf32(ar[0]);
                a[mt][1] = to_tf32(ar[8 * TS_ROW]);
                a[mt][2] = to_tf32(ar[4]);
                a[mt][3] = to_tf32(ar[8 * TS_ROW + 4]);
            }
#pragma unroll
            for (int nt = 0; nt < 4; nt++) {
                const float* br = Bsb + (wcol * 32 + nt * 8 + gid) * TS_ROW + kk + tg;
                b[nt][0] = to_tf32(br[0]);
                b[nt][1] = to_tf32(br[4]);
            }
#pragma unroll
            for (int mt = 0; mt < 4; mt++)
#pragma unroll
                for (int nt = 0; nt < 4; nt++)
                    MMA_TF32(c[mt][nt], a[mt][0], a[mt][1], a[mt][2], a[mt][3],
                             b[nt][0], b[nt][1]);
        }
        __syncthreads();
    }

#pragma unroll
    for (int mt = 0; mt < 4; mt++) {
        int row = by * 128 + wr * 64 + mt * 16 + gid;
#pragma unroll
        for (int nt = 0; nt < 4; nt++) {
            int col = bx * 128 + wcol * 32 + nt * 8 + 2 * tg;
            *reinterpret_cast<float2*>(&C[(size_t)row * N + col]) =
                make_float2(c[mt][nt][0], c[mt][nt][1]);
            *reinterpret_cast<float2*>(&C[(size_t)(row + 8) * N + col]) =
                make_float2(c[mt][nt][2], c[mt][nt][3]);
        }
    }
#undef TG_ISSUE
}

// ---------------- CPB MLP + per-head scale ----------------
__global__ void cpb_kernel(const float* __restrict__ w1, const float* __restrict__ b1,
                           const float* __restrict__ w2, const float* __restrict__ ls)
{
    int t = blockIdx.x * blockDim.x + threadIdx.x;
    if (t < 8) g_scale[t] = expf(fminf(ls[t], 4.605170185988091f)); // log(100)
    if (t >= 529) return;
    int a = t / 23, b = t % 23;
    float c0 = (float)(a - 11) * (8.0f / 7.0f);
    float c1 = (float)(b - 11) * (8.0f / 7.0f);
    const float inv_log8 = 0.4808983469629878f;
    float v0 = copysignf(log1pf(fabsf(c0)), c0) * inv_log8;
    float v1 = copysignf(log1pf(fabsf(c1)), c1) * inv_log8;
    float acc[8];
#pragma unroll
    for (int h = 0; h < 8; h++) acc[h] = 0.f;
    for (int j = 0; j < 512; j++) {
        float hv = fmaxf(fmaf(v0, w1[j], fmaf(v1, w1[512 + j], b1[j])), 0.f);
#pragma unroll
        for (int h = 0; h < 8; h++) acc[h] += hv * w2[j * 8 + h];
    }
#pragma unroll
    for (int h = 0; h < 8; h++)
        g_bias_tab[h * 529 + t] = 16.0f / (1.0f + expf(-acc[h]));
}

// ---------------- depthwise 3x3 conv + LayerNorm + qkv bias (vectorized) ----------------
// 192 threads, 4 contiguous channels per thread (float4 path)
__global__ __launch_bounds__(192) void convln_kernel(const float* __restrict__ qkv,
                                                     const float* __restrict__ wdw,
                                                     const float* __restrict__ lng,
                                                     const float* __restrict__ lnb,
                                                     const float* __restrict__ qb,
                                                     const float* __restrict__ vb,
                                                     float* __restrict__ out)
{
    int p  = blockIdx.x;
    int b  = p >> 14;
    int hh = (p >> 7) & 127;
    int ww = p & 127;
    int tid = threadIdx.x;
    int c4 = tid * 4;

    float4 acc = make_float4(0.f, 0.f, 0.f, 0.f);
#pragma unroll
    for (int dh = -1; dh <= 1; dh++) {
        int rr = hh + dh;
        if (rr < 0 || rr > 127) continue;
#pragma unroll
        for (int dw = -1; dw <= 1; dw++) {
            int col = ww + dw;
            if (col < 0 || col > 127) continue;
            float4 xv = *reinterpret_cast<const float4*>(
                qkv + ((size_t)((b * 128 + rr) * 128 + col)) * C3 + c4);
            float4 wv = *reinterpret_cast<const float4*>(
                wdw + ((dh + 1) * 3 + (dw + 1)) * C3 + c4);
            acc.x = fmaf(xv.x, wv.x, acc.x);
            acc.y = fmaf(xv.y, wv.y, acc.y);
            acc.z = fmaf(xv.z, wv.z, acc.z);
            acc.w = fmaf(xv.w, wv.w, acc.w);
        }
    }
    float s  = acc.x + acc.y + acc.z + acc.w;
    float sq = acc.x * acc.x + acc.y * acc.y + acc.z * acc.z + acc.w * acc.w;
#pragma unroll
    for (int off = 16; off > 0; off >>= 1) {
        s  += __shfl_xor_sync(0xffffffffu, s,  off);
        sq += __shfl_xor_sync(0xffffffffu, sq, off);
    }
    __shared__ float reds[6], redq[6];
    int wid = tid >> 5, lane = tid & 31;
    if (lane == 0) { reds[wid] = s; redq[wid] = sq; }
    __syncthreads();
    float st = 0.f, sqt = 0.f;
#pragma unroll
    for (int i = 0; i < 6; i++) { st += reds[i]; sqt += redq[i]; }
    float mu   = st * (1.0f / 768.0f);
    float var  = sqt * (1.0f / 768.0f) - mu * mu;
    float rstd = rsqrtf(var + 1e-5f);

    float4 gv = *reinterpret_cast<const float4*>(lng + c4);
    float4 bv = *reinterpret_cast<const float4*>(lnb + c4);
    float4 y;
    y.x = (acc.x - mu) * rstd * gv.x + bv.x;
    y.y = (acc.y - mu) * rstd * gv.y + bv.y;
    y.z = (acc.z - mu) * rstd * gv.z + bv.z;
    y.w = (acc.w - mu) * rstd * gv.w + bv.w;
    if (c4 < 256) {
        float4 qv = *reinterpret_cast<const float4*>(qb + c4);
        y.x += qv.x; y.y += qv.y; y.z += qv.z; y.w += qv.w;
    } else if (c4 >= 512) {
        float4 vv = *reinterpret_cast<const float4*>(vb + c4 - 512);
        y.x += vv.x; y.y += vv.y; y.z += vv.z; y.w += vv.w;
    }
    *reinterpret_cast<float4*>(out + (size_t)p * C3 + c4) = y;
}

// ---------------- fused windowed cosine attention (mma.sync tf32, 3x compensated) ----------------
// grid (512 windows, 8 heads), 256 threads = 8 warps.
// S phase: warp (wr2=wid>>1, wc2=wid&1) -> 16q x 64k tile, K=32 dims.
// PV phase: warp (wr2, wc2) -> 16q x 16d tile, K=128 keys per half.
__global__ __launch_bounds__(256) void attn_kernel(const float* __restrict__ qkv2,
                                                   float* __restrict__ out)
{
    extern __shared__ float sm[];
    float* Qn    = sm;                     // 64*36  = 2304
    float* Kn    = Qn + 64 * QN_S;         // 128*36 = 4608
    float* Vs    = Kn + 128 * KN_S;        // 128*40 = 5120
    float* Pt    = Vs + 128 * V_S;         // 64*132 = 8448
    float* lpart = Pt + 64 * P_S;          // 2*64   = 128
    float* tab   = lpart + 128;            // 529

    int widx = blockIdx.x, h = blockIdx.y;
    int b    = widx >> 8;
    int wrow = (widx >> 4) & 15;
    int wcol = widx & 15;
    int tid  = threadIdx.x;
    int wid  = tid >> 5, lane = tid & 31;
    int gid  = lane >> 2, tg = lane & 3;
    int wr2  = wid >> 1, wc2 = wid & 1;

    for (int t = tid; t < 529; t += 256) tab[t] = g_bias_tab[h * 529 + t];

    // ---- Q load (row-major [q][36]) then normalize*scale in place
    for (int t = tid; t < 512; t += 256) {
        int q = t >> 3, d4 = (t & 7) << 2;
        int pr = wrow * 8 + (q >> 3), pc = wcol * 8 + (q & 7);
        const float* p = qkv2 + ((size_t)((b * 128 + pr) * 128 + pc)) * C3 + h * HD + d4;
        *reinterpret_cast<float4*>(&Qn[q * QN_S + d4]) = *reinterpret_cast<const float4*>(p);
    }
    __syncthreads();
    if (tid < 64) {
        float4 v[8]; float ss = 0.f;
#pragma unroll
        for (int j = 0; j < 8; j++) {
            v[j] = *reinterpret_cast<const float4*>(&Qn[tid * QN_S + 4 * j]);
            ss += v[j].x * v[j].x + v[j].y * v[j].y + v[j].z * v[j].z + v[j].w * v[j].w;
        }
        float qm = rsqrtf(fmaxf(ss, 1.55e-5f)) * g_scale[h];
#pragma unroll
        for (int j = 0; j < 8; j++) {
            v[j].x *= qm; v[j].y *= qm; v[j].z *= qm; v[j].w *= qm;
            *reinterpret_cast<float4*>(&Qn[tid * QN_S + 4 * j]) = v[j];
        }
    }

    float cpv[2][4];  // PV accumulators: 16q x 16d warp tile, persists across halves
#pragma unroll
    for (int t = 0; t < 2; t++)
#pragma unroll
        for (int i = 0; i < 4; i++) cpv[t][i] = 0.f;

    for (int half = 0; half < 2; half++) {
        __syncthreads();  // Qn ready / previous half's Pt,Kn,Vs consumers done

        // ---- K/V load (row-major, zero-padded halo)
        int base_r = wrow * 8 - 4 + 8 * half, base_c = wcol * 8 - 4;
        for (int i = tid; i < 128 * 8; i += 256) {
            int kl = i >> 3, d4 = (i & 7) << 2;
            int gr = base_r + (kl >> 4), gc = base_c + (kl & 15);
            float4 k4 = make_float4(0.f, 0.f, 0.f, 0.f);
            float4 v4 = make_float4(0.f, 0.f, 0.f, 0.f);
            if (gr >= 0 && gr < 128 && gc >= 0 && gc < 128) {
                const float* p = qkv2 + ((size_t)((b * 128 + gr) * 128 + gc)) * C3 + Cc + h * HD + d4;
                k4 = *reinterpret_cast<const float4*>(p);
                v4 = *reinterpret_cast<const float4*>(p + Cc);
            }
            *reinterpret_cast<float4*>(&Kn[kl * KN_S + d4]) = k4;
            *reinterpret_cast<float4*>(&Vs[kl * V_S + d4]) = v4;
        }
        __syncthreads();

        // ---- normalize K rows
        if (tid < 128) {
            float4 v[8]; float ss = 0.f;
#pragma unroll
            for (int j = 0; j < 8; j++) {
                v[j] = *reinterpret_cast<const float4*>(&Kn[tid * KN_S + 4 * j]);
                ss += v[j].x * v[j].x + v[j].y * v[j].y + v[j].z * v[j].z + v[j].w * v[j].w;
            }
            float rm = rsqrtf(fmaxf(ss, 1.55e-5f));
#pragma unroll
            for (int j = 0; j < 8; j++) {
                v[j].x *= rm; v[j].y *= rm; v[j].z *= rm; v[j].w *= rm;
                *reinterpret_cast<float4*>(&Kn[tid * KN_S + 4 * j]) = v[j];
            }
        }
        __syncthreads();

        // ---- S phase: cs[8 ntiles][4], q rows wr2*16.., keys wc2*64..
        float cs[8][4];
#pragma unroll
        for (int t = 0; t < 8; t++)
#pragma unroll
            for (int i = 0; i < 4; i++) cs[t][i] = 0.f;

        int q0 = wr2 * 16;
#pragma unroll
        for (int kk = 0; kk < 32; kk += 8) {
            uint32_t ah[4], al[4];
            tf32_split(Qn[(q0 + gid) * QN_S + kk + tg],          ah[0], al[0]);
            tf32_split(Qn[(q0 + gid + 8) * QN_S + kk + tg],      ah[1], al[1]);
            tf32_split(Qn[(q0 + gid) * QN_S + kk + tg + 4],      ah[2], al[2]);
            tf32_split(Qn[(q0 + gid + 8) * QN_S + kk + tg + 4],  ah[3], al[3]);
#pragma unroll
            for (int t = 0; t < 8; t++) {
                int n0 = wc2 * 64 + t * 8;
                uint32_t bh[2], bl[2];
                tf32_split(Kn[(n0 + gid) * KN_S + kk + tg],     bh[0], bl[0]);
                tf32_split(Kn[(n0 + gid) * KN_S + kk + tg + 4], bh[1], bl[1]);
                MMA_TF32(cs[t], ah[0], ah[1], ah[2], ah[3], bh[0], bh[1]);
                MMA_TF32(cs[t], ah[0], ah[1], ah[2], ah[3], bl[0], bl[1]);
                MMA_TF32(cs[t], al[0], al[1], al[2], al[3], bh[0], bh[1]);
            }
        }

        // ---- bias + exp + store P + row sums
        int qa = q0 + gid, qb_ = qa + 8;
        int qra = qa >> 3, qca = qa & 7;
        int qrb = qb_ >> 3, qcb = qb_ & 7;
        float r0 = 0.f, r1 = 0.f;
#pragma unroll
        for (int t = 0; t < 8; t++) {
            int kl0 = wc2 * 64 + t * 8 + 2 * tg;
#pragma unroll
            for (int e = 0; e < 2; e++) {
                int kl = kl0 + e;
                int kr = (kl >> 4) + 8 * half, kc = kl & 15;
                float bias_a = tab[(qra - kr + 15) * 23 + (qca - kc + 15)];
                float bias_b = tab[(qrb - kr + 15) * 23 + (qcb - kc + 15)];
                float pa = __expf(cs[t][e]     + bias_a - 16.0f);
                float pb = __expf(cs[t][e + 2] + bias_b - 16.0f);
                cs[t][e]     = pa;  r0 += pa;
                cs[t][e + 2] = pb;  r1 += pb;
            }
            *reinterpret_cast<float2*>(&Pt[qa  * P_S + kl0]) = make_float2(cs[t][0], cs[t][1]);
            *reinterpret_cast<float2*>(&Pt[qb_ * P_S + kl0]) = make_float2(cs[t][2], cs[t][3]);
        }
        r0 += __shfl_xor_sync(0xffffffffu, r0, 1);
        r0 += __shfl_xor_sync(0xffffffffu, r0, 2);
        r1 += __shfl_xor_sync(0xffffffffu, r1, 1);
        r1 += __shfl_xor_sync(0xffffffffu, r1, 2);
        if (tg == 0) {
            if (half == 0) {
                lpart[wc2 * 64 + qa]  = r0;
                lpart[wc2 * 64 + qb_] = r1;
            } else {
                lpart[wc2 * 64 + qa]  += r0;
                lpart[wc2 * 64 + qb_] += r1;
            }
        }
        __syncthreads();

        // ---- PV phase: q rows wr2*16.., d cols wc2*16.., K = 128 keys
#pragma unroll 4
        for (int kk = 0; kk < 128; kk += 8) {
            uint32_t ah[4], al[4];
            tf32_split(Pt[(q0 + gid) * P_S + kk + tg],          ah[0], al[0]);
            tf32_split(Pt[(q0 + gid + 8) * P_S + kk + tg],      ah[1], al[1]);
            tf32_split(Pt[(q0 + gid) * P_S + kk + tg + 4],      ah[2], al[2]);
            tf32_split(Pt[(q0 + gid + 8) * P_S + kk + tg + 4],  ah[3], al[3]);
#pragma unroll
            for (int t = 0; t < 2; t++) {
                int d0 = wc2 * 16 + t * 8;
                uint32_t bh[2], bl[2];
                tf32_split(Vs[(kk + tg) * V_S + d0 + gid],     bh[0], bl[0]);
                tf32_split(Vs[(kk + tg + 4) * V_S + d0 + gid], bh[1], bl[1]);
                MMA_TF32(cpv[t], ah[0], ah[1], ah[2], ah[3], bh[0], bh[1]);
                MMA_TF32(cpv[t], ah[0], ah[1], ah[2], ah[3], bl[0], bl[1]);
                MMA_TF32(cpv[t], al[0], al[1], al[2], al[3], bh[0], bh[1]);
            }
        }
    }

    __syncthreads();  // lpart final

    // ---- epilogue: divide by row sums, store
    int qa = wr2 * 16 + gid, qb_ = qa + 8;
    float linv0 = 1.0f / (lpart[qa]  + lpart[64 + qa]);
    float linv1 = 1.0f / (lpart[qb_] + lpart[64 + qb_]);
    int pra = wrow * 8 + (qa >> 3),  pca = wcol * 8 + (qa & 7);
    int prb = wrow * 8 + (qb_ >> 3), pcb = wcol * 8 + (qb_ & 7);
    float* opa = out + ((size_t)((b * 128 + pra) * 128 + pca)) * Cc + h * HD;
    float* opb = out + ((size_t)((b * 128 + prb) * 128 + pcb)) * Cc + h * HD;
#pragma unroll
    for (int t = 0; t < 2; t++) {
        int d = wc2 * 16 + t * 8 + 2 * tg;
        *reinterpret_cast<float2*>(opa + d) = make_float2(cpv[t][0] * linv0, cpv[t][1] * linv0);
        *reinterpret_cast<float2*>(opb + d) = make_float2(cpv[t][2] * linv1, cpv[t][3] * linv1);
    }
}

// ---------------- launch ----------------
extern "C" void kernel_launch(void* const* d_in, const int* in_sizes, int n_in,
                              void* d_out, int out_size)
{
    const float* x           = (const float*)d_in[0];
    const float* w_qkv       = (const float*)d_in[1];
    const float* w_dw        = (const float*)d_in[2];
    const float* ln_g        = (const float*)d_in[3];
    const float* ln_b        = (const float*)d_in[4];
    const float* q_bias      = (const float*)d_in[5];
    const float* v_bias      = (const float*)d_in[6];
    const float* logit_scale = (const float*)d_in[7];
    const float* cpb_w1      = (const float*)d_in[8];
    const float* cpb_b1      = (const float*)d_in[9];
    const float* cpb_w2      = (const float*)d_in[10];
    const float* w_proj      = (const float*)d_in[11];
    float* out = (float*)d_out;

    float *p_qkv, *p_qkv2, *p_att, *p_wqkvT, *p_wprojT;
    cudaGetSymbolAddress((void**)&p_qkv,   g_qkv);
    cudaGetSymbolAddress((void**)&p_qkv2,  g_qkv2);
    cudaGetSymbolAddress((void**)&p_att,   g_att);
    cudaGetSymbolAddress((void**)&p_wqkvT, g_wqkvT);
    cudaGetSymbolAddress((void**)&p_wprojT,g_wprojT);

    const int ATTN_SMEM = (64 * QN_S + 128 * KN_S + 128 * V_S + 64 * P_S + 128 + 529) * 4;
    cudaFuncSetAttribute(attn_kernel, cudaFuncAttributeMaxDynamicSharedMemorySize, ATTN_SMEM);
    cudaFuncSetAttribute(tgemm, cudaFuncAttributeMaxDynamicSharedMemorySize, TG_SMEM_B);

    // 0) transpose weights to [N][K] K-major
    transpose_kernel<<<(Cc * C3 + 255) / 256, 256>>>(w_qkv, p_wqkvT, Cc, C3);
    transpose_kernel<<<(Cc * Cc + 255) / 256, 256>>>(w_proj, p_wprojT, Cc, Cc);

    // 1) CPB bias table + per-head scales
    cpb_kernel<<<5, 128>>>(cpb_w1, cpb_b1, cpb_w2, logit_scale);

    // 2) qkv = x @ w_qkv  (mma.sync tf32)
    tgemm<<<dim3(C3 / 128, NPIX / 128), 256, TG_SMEM_B>>>(x, p_wqkvT, p_qkv, C3);

    // 3) depthwise conv + LN + bias (vectorized)
    convln_kernel<<<NPIX, 192>>>(p_qkv, w_dw, ln_g, ln_b, q_bias, v_bias, p_qkv2);

    // 4) fused windowed attention (mma.sync tf32, error-compensated)
    attn_kernel<<<dim3(NWIN, HEADS), 256, ATTN_SMEM>>>(p_qkv2, p_att);

    // 5) out = att @ w_proj  (mma.sync tf32)
    tgemm<<<dim3(Cc / 128, NPIX / 128), 256, TG_SMEM_B>>>(p_att, p_wprojT, out, Cc);
}

// round 15
// speedup vs baseline: 2.0988x; 1.0600x over previous
#include <cuda_runtime.h>
#include <cuda_bf16.h>
#include <cstdint>
#include <cstddef>

#define Bc 2
#define Hc 128
#define Wc 128
#define Cc 256
#define C3 768
#define NPIX (Bc*Hc*Wc)           // 32768
#define HEADS 8
#define HD 32
#define WS 8
#define KW 16
#define NWIN 512                  // B * 16 * 16
#define GK 256                    // GEMM K (both GEMMs)

// tgemm smem: [128 rows][36 floats] per operand per stage
#define TS_ROW 36
#define TG_STAGE_F (2 * 128 * TS_ROW)
#define TG_SMEM_B  (2 * TG_STAGE_F * 4)        // 73728 bytes

// ---- attn smem word-offsets (units: 4B words) ----
// raw region (overlaid by P after consumption):
#define O_QRAW 0        // Qraw[64][36] f32
#define O_KRAW 2304     // Kraw[128][36] f32
#define O_VRAW 6912     // Vraw[128][40] f32   (raw region ends 12032)
#define O_PHI  0        // Phi[64][68] bf16x2 words (4352)
#define O_PLO  4352     // Plo[64][68]          (ends 8704 <= 12032)
// split region:
#define O_QHI  12032    // Qhi[64][20]
#define O_QLO  13312
#define O_KHI  14592    // Khi[128][20]
#define O_KLO  17152
#define O_VTHI 19712    // Vthi[32][68]  (V transposed: [d][k-pairs])
#define O_VTLO 21888
#define O_LPART 24064   // 128
#define O_TAB  24192    // 529
#define ATTN_WORDS 24721
#define KQW 20          // Q/K row stride in words (bank: 20g+tg distinct mod 32)
#define PVW 68          // P/Vt row stride in words (bank: 4g+tg)

// ---------------- scratch (device globals; no allocation) ----------------
__device__ __align__(16) float g_qkv [(size_t)NPIX * C3];
__device__ __align__(16) float g_qkv2[(size_t)NPIX * C3];
__device__ __align__(16) float g_att [(size_t)NPIX * Cc];
__device__ __align__(16) float g_wqkvT[(size_t)C3 * Cc];
__device__ __align__(16) float g_wprojT[(size_t)Cc * Cc];
__device__ __align__(16) float g_bias_tab[8 * 529];
__device__ float g_scale[8];

// ---------------- helpers ----------------
__device__ __forceinline__ uint32_t smem_u32(const void* p) {
    uint32_t a;
    asm("{ .reg .u64 t; cvta.to.shared.u64 t, %1; cvt.u32.u64 %0, t; }" : "=r"(a) : "l"(p));
    return a;
}
__device__ __forceinline__ uint32_t to_tf32(float f) {
    uint32_t r;
    asm("cvt.rna.tf32.f32 %0, %1;" : "=r"(r) : "f"(f));
    return r;
}
// pack (a,b) into bf16x2 hi word + bf16x2 lo (residual) word
__device__ __forceinline__ void bf16_split2(float a, float b, uint32_t& hi, uint32_t& lo) {
    __nv_bfloat162 h = __floats2bfloat162_rn(a, b);
    float ra = a - __bfloat162float(h.x);
    float rb = b - __bfloat162float(h.y);
    __nv_bfloat162 l = __floats2bfloat162_rn(ra, rb);
    hi = *reinterpret_cast<uint32_t*>(&h);
    lo = *reinterpret_cast<uint32_t*>(&l);
}
#define MMA_TF32(c, a0,a1,a2,a3, b0,b1) \
    asm volatile("mma.sync.aligned.m16n8k8.row.col.f32.tf32.tf32.f32 " \
        "{%0,%1,%2,%3}, {%4,%5,%6,%7}, {%8,%9}, {%0,%1,%2,%3};" \
        : "+f"((c)[0]), "+f"((c)[1]), "+f"((c)[2]), "+f"((c)[3]) \
        : "r"(a0), "r"(a1), "r"(a2), "r"(a3), "r"(b0), "r"(b1))
#define MMA_BF16(c, a0,a1,a2,a3, b0,b1) \
    asm volatile("mma.sync.aligned.m16n8k16.row.col.f32.bf16.bf16.f32 " \
        "{%0,%1,%2,%3}, {%4,%5,%6,%7}, {%8,%9}, {%0,%1,%2,%3};" \
        : "+f"((c)[0]), "+f"((c)[1]), "+f"((c)[2]), "+f"((c)[3]) \
        : "r"(a0), "r"(a1), "r"(a2), "r"(a3), "r"(b0), "r"(b1))

#define CP_ASYNC16(dst, src) asm volatile("cp.async.cg.shared.global [%0], [%1], 16;" :: "r"(dst), "l"(src) : "memory")
#define CP_COMMIT()          asm volatile("cp.async.commit_group;" ::: "memory")
#define CP_WAIT(n)           asm volatile("cp.async.wait_group %0;" :: "n"(n) : "memory")

// ---------------- weight transpose (tiny) ----------------
__global__ void transpose_kernel(const float* __restrict__ W, float* __restrict__ WT,
                                 int K, int N)
{
    int i = blockIdx.x * 256 + threadIdx.x;
    if (i >= K * N) return;
    int k = i / N, n = i % N;
    WT[(size_t)n * K + k] = W[i];
}

// ---------------- mma.sync tf32 GEMM: C[M,N] = A[M,GK] * Bt[N,GK]^T ----------------
__global__ __launch_bounds__(256, 2) void tgemm(const float* __restrict__ A,
                                                const float* __restrict__ Bt,
                                                float* __restrict__ C, int N)
{
    extern __shared__ float sm[];
    uint32_t sb = smem_u32(sm);

    int tid  = threadIdx.x;
    int wid  = tid >> 5, lane = tid & 31;
    int gid  = lane >> 2, tg = lane & 3;
    int wr   = wid >> 2, wcol = wid & 3;
    int bx = blockIdx.x, by = blockIdx.y;

    const float* Ab = A  + (size_t)(by * 128) * GK;
    const float* Bb = Bt + (size_t)(bx * 128) * GK;

    float c[4][4][4];
#pragma unroll
    for (int mt = 0; mt < 4; mt++)
#pragma unroll
        for (int nt = 0; nt < 4; nt++)
#pragma unroll
            for (int i = 0; i < 4; i++) c[mt][nt][i] = 0.f;

    int ld_row = tid >> 3, ld_c4 = tid & 7;

#define TG_ISSUE(kt) do { \
        int _bs = (kt) & 1; \
        uint32_t _ab = sb + _bs * (TG_STAGE_F * 4); \
        uint32_t _bbx = _ab + 128 * TS_ROW * 4; \
        const float* _ga = Ab + (kt) * 32; \
        const float* _gb = Bb + (kt) * 32; \
        _Pragma("unroll") \
        for (int _it = 0; _it < 4; _it++) { \
            int _row = ld_row + _it * 32; \
            uint32_t _off = (_row * TS_ROW + ld_c4 * 4) * 4; \
            CP_ASYNC16(_ab  + _off, _ga + (size_t)_row * GK + ld_c4 * 4); \
            CP_ASYNC16(_bbx + _off, _gb + (size_t)_row * GK + ld_c4 * 4); \
        } \
        CP_COMMIT(); \
    } while (0)

    TG_ISSUE(0);

    for (int kt = 0; kt < 8; kt++) {
        if (kt + 1 < 8) { TG_ISSUE(kt + 1); CP_WAIT(1); }
        else            { CP_WAIT(0); }
        __syncthreads();

        const float* Asb = sm + (kt & 1) * TG_STAGE_F;
        const float* Bsb = Asb + 128 * TS_ROW;

#pragma unroll
        for (int kk = 0; kk < 32; kk += 8) {
            uint32_t a[4][4], b[4][2];
#pragma unroll
            for (int mt = 0; mt < 4; mt++) {
                const float* ar = Asb + (wr * 64 + mt * 16 + gid) * TS_ROW + kk + tg;
                a[mt][0] = to_tf32(ar[0]);
                a[mt][1] = to_tf32(ar[8 * TS_ROW]);
                a[mt][2] = to_tf32(ar[4]);
                a[mt][3] = to_tf32(ar[8 * TS_ROW + 4]);
            }
#pragma unroll
            for (int nt = 0; nt < 4; nt++) {
                const float* br = Bsb + (wcol * 32 + nt * 8 + gid) * TS_ROW + kk + tg;
                b[nt][0] = to_tf32(br[0]);
                b[nt][1] = to_tf32(br[4]);
            }
#pragma unroll
            for (int mt = 0; mt < 4; mt++)
#pragma unroll
                for (int nt = 0; nt < 4; nt++)
                    MMA_TF32(c[mt][nt], a[mt][0], a[mt][1], a[mt][2], a[mt][3],
                             b[nt][0], b[nt][1]);
        }
        __syncthreads();
    }

#pragma unroll
    for (int mt = 0; mt < 4; mt++) {
        int row = by * 128 + wr * 64 + mt * 16 + gid;
#pragma unroll
        for (int nt = 0; nt < 4; nt++) {
            int col = bx * 128 + wcol * 32 + nt * 8 + 2 * tg;
            *reinterpret_cast<float2*>(&C[(size_t)row * N + col]) =
                make_float2(c[mt][nt][0], c[mt][nt][1]);
            *reinterpret_cast<float2*>(&C[(size_t)(row + 8) * N + col]) =
                make_float2(c[mt][nt][2], c[mt][nt][3]);
        }
    }
#undef TG_ISSUE
}

// ---------------- CPB MLP + per-head scale ----------------
__global__ void cpb_kernel(const float* __restrict__ w1, const float* __restrict__ b1,
                           const float* __restrict__ w2, const float* __restrict__ ls)
{
    int t = blockIdx.x * blockDim.x + threadIdx.x;
    if (t < 8) g_scale[t] = expf(fminf(ls[t], 4.605170185988091f)); // log(100)
    if (t >= 529) return;
    int a = t / 23, b = t % 23;
    float c0 = (float)(a - 11) * (8.0f / 7.0f);
    float c1 = (float)(b - 11) * (8.0f / 7.0f);
    const float inv_log8 = 0.4808983469629878f;
    float v0 = copysignf(log1pf(fabsf(c0)), c0) * inv_log8;
    float v1 = copysignf(log1pf(fabsf(c1)), c1) * inv_log8;
    float acc[8];
#pragma unroll
    for (int h = 0; h < 8; h++) acc[h] = 0.f;
    for (int j = 0; j < 512; j++) {
        float hv = fmaxf(fmaf(v0, w1[j], fmaf(v1, w1[512 + j], b1[j])), 0.f);
#pragma unroll
        for (int h = 0; h < 8; h++) acc[h] += hv * w2[j * 8 + h];
    }
#pragma unroll
    for (int h = 0; h < 8; h++)
        g_bias_tab[h * 529 + t] = 16.0f / (1.0f + expf(-acc[h]));
}

// ---------------- depthwise 3x3 conv + LayerNorm + bias: row-sweep register ring ----------------
// block = half row (64 cols), 192 threads (one float4 channel group each)
__global__ __launch_bounds__(192) void convln_kernel(const float* __restrict__ qkv,
                                                     const float* __restrict__ wdw,
                                                     const float* __restrict__ lng,
                                                     const float* __restrict__ lnb,
                                                     const float* __restrict__ qb,
                                                     const float* __restrict__ vb,
                                                     float* __restrict__ out)
{
    int blk  = blockIdx.x;           // 512 = b(2) * h(128) * half(2)
    int half = blk & 1;
    int hh   = (blk >> 1) & 127;
    int b    = blk >> 8;
    int tid  = threadIdx.x;
    int c4   = tid * 4;
    int wid  = tid >> 5, lane = tid & 31;

    // weights + LN params hoisted (loaded once)
    float4 wt[9];
#pragma unroll
    for (int i = 0; i < 9; i++)
        wt[i] = *reinterpret_cast<const float4*>(wdw + i * C3 + c4);
    float4 gv = *reinterpret_cast<const float4*>(lng + c4);
    float4 bb = *reinterpret_cast<const float4*>(lnb + c4);
    if (c4 < 256) {
        float4 qv = *reinterpret_cast<const float4*>(qb + c4);
        bb.x += qv.x; bb.y += qv.y; bb.z += qv.z; bb.w += qv.w;
    } else if (c4 >= 512) {
        float4 vv = *reinterpret_cast<const float4*>(vb + c4 - 512);
        bb.x += vv.x; bb.y += vv.y; bb.z += vv.z; bb.w += vv.w;
    }

    __shared__ float reds[2][6], redq[2][6];

    const float4 z4 = make_float4(0.f, 0.f, 0.f, 0.f);
    float4 ring[3][3];   // [col slot: w-1,w,w+1][row: hh-1,hh,hh+1]

#define LOADCOL(col, dst) do { \
        if ((col) < 0 || (col) > 127) { dst[0] = z4; dst[1] = z4; dst[2] = z4; } \
        else { \
            _Pragma("unroll") \
            for (int _i = 0; _i < 3; _i++) { \
                int _r = hh - 1 + _i; \
                dst[_i] = (_r >= 0 && _r <= 127) \
                    ? *reinterpret_cast<const float4*>(qkv + ((size_t)((b * 128 + _r) * 128 + (col))) * C3 + c4) \
                    : z4; \
            } \
        } \
    } while (0)

    int w0 = half * 64;
    LOADCOL(w0 - 1, ring[0]);
    LOADCOL(w0,     ring[1]);

    for (int w = w0; w < w0 + 64; w++) {
        LOADCOL(w + 1, ring[2]);

        float4 acc = z4;
#pragma unroll
        for (int dc = 0; dc < 3; dc++)
#pragma unroll
            for (int dr = 0; dr < 3; dr++) {
                float4 xv = ring[dc][dr];
                float4 wv = wt[dr * 3 + dc];
                acc.x = fmaf(xv.x, wv.x, acc.x);
                acc.y = fmaf(xv.y, wv.y, acc.y);
                acc.z = fmaf(xv.z, wv.z, acc.z);
                acc.w = fmaf(xv.w, wv.w, acc.w);
            }

        float s  = acc.x + acc.y + acc.z + acc.w;
        float sq = acc.x * acc.x + acc.y * acc.y + acc.z * acc.z + acc.w * acc.w;
#pragma unroll
        for (int off = 16; off > 0; off >>= 1) {
            s  += __shfl_xor_sync(0xffffffffu, s,  off);
            sq += __shfl_xor_sync(0xffffffffu, sq, off);
        }
        int par = w & 1;
        if (lane == 0) { reds[par][wid] = s; redq[par][wid] = sq; }
        __syncthreads();
        float st = 0.f, sqt = 0.f;
#pragma unroll
        for (int i = 0; i < 6; i++) { st += reds[par][i]; sqt += redq[par][i]; }
        float mu   = st * (1.0f / 768.0f);
        float var  = sqt * (1.0f / 768.0f) - mu * mu;
        float rstd = rsqrtf(var + 1e-5f);

        float4 y;
        y.x = (acc.x - mu) * rstd * gv.x + bb.x;
        y.y = (acc.y - mu) * rstd * gv.y + bb.y;
        y.z = (acc.z - mu) * rstd * gv.z + bb.z;
        y.w = (acc.w - mu) * rstd * gv.w + bb.w;
        *reinterpret_cast<float4*>(out + ((size_t)((b * 128 + hh) * 128 + w)) * C3 + c4) = y;

        ring[0][0] = ring[1][0]; ring[0][1] = ring[1][1]; ring[0][2] = ring[1][2];
        ring[1][0] = ring[2][0]; ring[1][1] = ring[2][1]; ring[1][2] = ring[2][2];
    }
#undef LOADCOL
}

// ---------------- fused windowed cosine attention (bf16 hi/lo, m16n8k16, precomputed splits) ----------------
__global__ __launch_bounds__(256) void attn_kernel(const float* __restrict__ qkv2,
                                                   float* __restrict__ out)
{
    extern __shared__ float smf[];
    uint32_t* smu = reinterpret_cast<uint32_t*>(smf);

    int widx = blockIdx.x, h = blockIdx.y;
    int b    = widx >> 8;
    int wrow = (widx >> 4) & 15;
    int wcol = widx & 15;
    int tid  = threadIdx.x;
    int wid  = tid >> 5, lane = tid & 31;
    int gid  = lane >> 2, tg = lane & 3;
    int wr2  = wid >> 1, wc2 = wid & 1;

    for (int t = tid; t < 529; t += 256) smf[O_TAB + t] = g_bias_tab[h * 529 + t];

    // ---- Q raw load [q][36]
    for (int t = tid; t < 512; t += 256) {
        int q = t >> 3, d4 = (t & 7) << 2;
        int pr = wrow * 8 + (q >> 3), pc = wcol * 8 + (q & 7);
        const float* p = qkv2 + ((size_t)((b * 128 + pr) * 128 + pc)) * C3 + h * HD + d4;
        *reinterpret_cast<float4*>(&smf[O_QRAW + q * 36 + d4]) = *reinterpret_cast<const float4*>(p);
    }
    __syncthreads();
    // ---- Q normalize*scale -> split bf16 hi/lo [q][20 words]
    if (tid < 64) {
        float v[32]; float ss = 0.f;
#pragma unroll
        for (int d = 0; d < 32; d++) { v[d] = smf[O_QRAW + tid * 36 + d]; ss = fmaf(v[d], v[d], ss); }
        float qm = rsqrtf(fmaxf(ss, 1.55e-5f)) * g_scale[h];
#pragma unroll
        for (int j = 0; j < 16; j++) {
            uint32_t hi, lo;
            bf16_split2(v[2 * j] * qm, v[2 * j + 1] * qm, hi, lo);
            smu[O_QHI + tid * KQW + j] = hi;
            smu[O_QLO + tid * KQW + j] = lo;
        }
    }

    float cpv[2][4];
#pragma unroll
    for (int t = 0; t < 2; t++)
#pragma unroll
        for (int i = 0; i < 4; i++) cpv[t][i] = 0.f;

    int q0 = wr2 * 16;

    for (int half = 0; half < 2; half++) {
        __syncthreads();  // prior PV done with P/Vt; Q split visible

        // ---- raw K/V load (zero-padded halo): Kraw[kl][36], Vraw[kl][40]
        int base_r = wrow * 8 - 4 + 8 * half, base_c = wcol * 8 - 4;
        for (int i = tid; i < 128 * 8; i += 256) {
            int kl = i >> 3, d4 = (i & 7) << 2;
            int gr = base_r + (kl >> 4), gc = base_c + (kl & 15);
            float4 k4 = make_float4(0.f, 0.f, 0.f, 0.f);
            float4 v4 = make_float4(0.f, 0.f, 0.f, 0.f);
            if (gr >= 0 && gr < 128 && gc >= 0 && gc < 128) {
                const float* p = qkv2 + ((size_t)((b * 128 + gr) * 128 + gc)) * C3 + Cc + h * HD + d4;
                k4 = *reinterpret_cast<const float4*>(p);
                v4 = *reinterpret_cast<const float4*>(p + Cc);
            }
            *reinterpret_cast<float4*>(&smf[O_KRAW + kl * 36 + d4]) = k4;
            *reinterpret_cast<float4*>(&smf[O_VRAW + kl * 40 + d4]) = v4;
        }
        __syncthreads();

        // ---- K normalize -> split [n][20 words]
        if (tid < 128) {
            float v[32]; float ss = 0.f;
#pragma unroll
            for (int d = 0; d < 32; d++) { v[d] = smf[O_KRAW + tid * 36 + d]; ss = fmaf(v[d], v[d], ss); }
            float rm = rsqrtf(fmaxf(ss, 1.55e-5f));
#pragma unroll
            for (int j = 0; j < 16; j++) {
                uint32_t hi, lo;
                bf16_split2(v[2 * j] * rm, v[2 * j + 1] * rm, hi, lo);
                smu[O_KHI + tid * KQW + j] = hi;
                smu[O_KLO + tid * KQW + j] = lo;
            }
        }
        // ---- V transpose + split: Vt[d][k-pair word]  (d rows of PVW words)
        for (int i = tid; i < 32 * 64; i += 256) {
            int d  = i & 31;
            int k2 = i >> 5;
            float v0 = smf[O_VRAW + (2 * k2)     * 40 + d];
            float v1 = smf[O_VRAW + (2 * k2 + 1) * 40 + d];
            uint32_t hi, lo;
            bf16_split2(v0, v1, hi, lo);
            smu[O_VTHI + d * PVW + k2] = hi;
            smu[O_VTLO + d * PVW + k2] = lo;
        }
        __syncthreads();

        // ---- S phase: q rows q0..q0+15, keys wc2*64.. (K=32, 2 k16-steps)
        float cs[8][4];
#pragma unroll
        for (int t = 0; t < 8; t++)
#pragma unroll
            for (int i = 0; i < 4; i++) cs[t][i] = 0.f;

#pragma unroll
        for (int ks = 0; ks < 2; ks++) {
            int w0 = ks * 8 + tg;
            uint32_t ah[4], al[4];
            ah[0] = smu[O_QHI + (q0 + gid)     * KQW + w0];
            ah[1] = smu[O_QHI + (q0 + gid + 8) * KQW + w0];
            ah[2] = smu[O_QHI + (q0 + gid)     * KQW + w0 + 4];
            ah[3] = smu[O_QHI + (q0 + gid + 8) * KQW + w0 + 4];
            al[0] = smu[O_QLO + (q0 + gid)     * KQW + w0];
            al[1] = smu[O_QLO + (q0 + gid + 8) * KQW + w0];
            al[2] = smu[O_QLO + (q0 + gid)     * KQW + w0 + 4];
            al[3] = smu[O_QLO + (q0 + gid + 8) * KQW + w0 + 4];
#pragma unroll
            for (int t = 0; t < 8; t++) {
                int n0 = wc2 * 64 + t * 8;
                uint32_t bh0 = smu[O_KHI + (n0 + gid) * KQW + w0];
                uint32_t bh1 = smu[O_KHI + (n0 + gid) * KQW + w0 + 4];
                uint32_t bl0 = smu[O_KLO + (n0 + gid) * KQW + w0];
                uint32_t bl1 = smu[O_KLO + (n0 + gid) * KQW + w0 + 4];
                MMA_BF16(cs[t], ah[0], ah[1], ah[2], ah[3], bh0, bh1);
                MMA_BF16(cs[t], ah[0], ah[1], ah[2], ah[3], bl0, bl1);
                MMA_BF16(cs[t], al[0], al[1], al[2], al[3], bh0, bh1);
            }
        }

        // ---- bias + exp + row sums; store P as bf16 hi/lo
        int qa = q0 + gid, qb_ = qa + 8;
        int qra = qa >> 3, qca = qa & 7;
        int qrb = qb_ >> 3, qcb = qb_ & 7;
        float r0 = 0.f, r1 = 0.f;
#pragma unroll
        for (int t = 0; t < 8; t++) {
            int kl0 = wc2 * 64 + t * 8 + 2 * tg;
#pragma unroll
            for (int e = 0; e < 2; e++) {
                int kl = kl0 + e;
                int kr = (kl >> 4) + 8 * half, kc = kl & 15;
                float bias_a = smf[O_TAB + (qra - kr + 15) * 23 + (qca - kc + 15)];
                float bias_b = smf[O_TAB + (qrb - kr + 15) * 23 + (qcb - kc + 15)];
                float pa = __expf(cs[t][e]     + bias_a - 16.0f);
                float pb = __expf(cs[t][e + 2] + bias_b - 16.0f);
                cs[t][e]     = pa;  r0 += pa;
                cs[t][e + 2] = pb;  r1 += pb;
            }
            uint32_t hia, loa, hib, lob;
            bf16_split2(cs[t][0], cs[t][1], hia, loa);
            bf16_split2(cs[t][2], cs[t][3], hib, lob);
            smu[O_PHI + qa  * PVW + (kl0 >> 1)] = hia;
            smu[O_PLO + qa  * PVW + (kl0 >> 1)] = loa;
            smu[O_PHI + qb_ * PVW + (kl0 >> 1)] = hib;
            smu[O_PLO + qb_ * PVW + (kl0 >> 1)] = lob;
        }
        r0 += __shfl_xor_sync(0xffffffffu, r0, 1);
        r0 += __shfl_xor_sync(0xffffffffu, r0, 2);
        r1 += __shfl_xor_sync(0xffffffffu, r1, 1);
        r1 += __shfl_xor_sync(0xffffffffu, r1, 2);
        if (tg == 0) {
            if (half == 0) {
                smf[O_LPART + wc2 * 64 + qa]  = r0;
                smf[O_LPART + wc2 * 64 + qb_] = r1;
            } else {
                smf[O_LPART + wc2 * 64 + qa]  += r0;
                smf[O_LPART + wc2 * 64 + qb_] += r1;
            }
        }
        __syncthreads();

        // ---- PV: q rows q0.., d cols wc2*16.., K=128 keys (8 k16-steps)
#pragma unroll 2
        for (int ks = 0; ks < 8; ks++) {
            int w0 = ks * 8 + tg;
            uint32_t ah[4], al[4];
            ah[0] = smu[O_PHI + (q0 + gid)     * PVW + w0];
            ah[1] = smu[O_PHI + (q0 + gid + 8) * PVW + w0];
            ah[2] = smu[O_PHI + (q0 + gid)     * PVW + w0 + 4];
            ah[3] = smu[O_PHI + (q0 + gid + 8) * PVW + w0 + 4];
            al[0] = smu[O_PLO + (q0 + gid)     * PVW + w0];
            al[1] = smu[O_PLO + (q0 + gid + 8) * PVW + w0];
            al[2] = smu[O_PLO + (q0 + gid)     * PVW + w0 + 4];
            al[3] = smu[O_PLO + (q0 + gid + 8) * PVW + w0 + 4];
#pragma unroll
            for (int t = 0; t < 2; t++) {
                int d0 = wc2 * 16 + t * 8;
                uint32_t bh0 = smu[O_VTHI + (d0 + gid) * PVW + w0];
                uint32_t bh1 = smu[O_VTHI + (d0 + gid) * PVW + w0 + 4];
                uint32_t bl0 = smu[O_VTLO + (d0 + gid) * PVW + w0];
                uint32_t bl1 = smu[O_VTLO + (d0 + gid) * PVW + w0 + 4];
                MMA_BF16(cpv[t], ah[0], ah[1], ah[2], ah[3], bh0, bh1);
                MMA_BF16(cpv[t], ah[0], ah[1], ah[2], ah[3], bl0, bl1);
                MMA_BF16(cpv[t], al[0], al[1], al[2], al[3], bh0, bh1);
            }
        }
    }

    __syncthreads();

    // ---- epilogue
    int qa = wr2 * 16 + gid, qb_ = qa + 8;
    float linv0 = 1.0f / (smf[O_LPART + qa]  + smf[O_LPART + 64 + qa]);
    float linv1 = 1.0f / (smf[O_LPART + qb_] + smf[O_LPART + 64 + qb_]);
    int pra = wrow * 8 + (qa >> 3),  pca = wcol * 8 + (qa & 7);
    int prb = wrow * 8 + (qb_ >> 3), pcb = wcol * 8 + (qb_ & 7);
    float* opa = out + ((size_t)((b * 128 + pra) * 128 + pca)) * Cc + h * HD;
    float* opb = out + ((size_t)((b * 128 + prb) * 128 + pcb)) * Cc + h * HD;
#pragma unroll
    for (int t = 0; t < 2; t++) {
        int d = wc2 * 16 + t * 8 + 2 * tg;
        *reinterpret_cast<float2*>(opa + d) = make_float2(cpv[t][0] * linv0, cpv[t][1] * linv0);
        *reinterpret_cast<float2*>(opb + d) = make_float2(cpv[t][2] * linv1, cpv[t][3] * linv1);
    }
}

// ---------------- launch ----------------
extern "C" void kernel_launch(void* const* d_in, const int* in_sizes, int n_in,
                              void* d_out, int out_size)
{
    const float* x           = (const float*)d_in[0];
    const float* w_qkv       = (const float*)d_in[1];
    const float* w_dw        = (const float*)d_in[2];
    const float* ln_g        = (const float*)d_in[3];
    const float* ln_b        = (const float*)d_in[4];
    const float* q_bias      = (const float*)d_in[5];
    const float* v_bias      = (const float*)d_in[6];
    const float* logit_scale = (const float*)d_in[7];
    const float* cpb_w1      = (const float*)d_in[8];
    const float* cpb_b1      = (const float*)d_in[9];
    const float* cpb_w2      = (const float*)d_in[10];
    const float* w_proj      = (const float*)d_in[11];
    float* out = (float*)d_out;

    float *p_qkv, *p_qkv2, *p_att, *p_wqkvT, *p_wprojT;
    cudaGetSymbolAddress((void**)&p_qkv,   g_qkv);
    cudaGetSymbolAddress((void**)&p_qkv2,  g_qkv2);
    cudaGetSymbolAddress((void**)&p_att,   g_att);
    cudaGetSymbolAddress((void**)&p_wqkvT, g_wqkvT);
    cudaGetSymbolAddress((void**)&p_wprojT,g_wprojT);

    const int ATTN_SMEM = ATTN_WORDS * 4;   // 98884 B
    cudaFuncSetAttribute(attn_kernel, cudaFuncAttributeMaxDynamicSharedMemorySize, ATTN_SMEM);
    cudaFuncSetAttribute(tgemm, cudaFuncAttributeMaxDynamicSharedMemorySize, TG_SMEM_B);

    // 0) transpose weights to [N][K] K-major
    transpose_kernel<<<(Cc * C3 + 255) / 256, 256>>>(w_qkv, p_wqkvT, Cc, C3);
    transpose_kernel<<<(Cc * Cc + 255) / 256, 256>>>(w_proj, p_wprojT, Cc, Cc);

    // 1) CPB bias table + per-head scales
    cpb_kernel<<<5, 128>>>(cpb_w1, cpb_b1, cpb_w2, logit_scale);

    // 2) qkv = x @ w_qkv  (mma.sync tf32)
    tgemm<<<dim3(C3 / 128, NPIX / 128), 256, TG_SMEM_B>>>(x, p_wqkvT, p_qkv, C3);

    // 3) depthwise conv + LN + bias (row-sweep register ring)
    convln_kernel<<<512, 192>>>(p_qkv, w_dw, ln_g, ln_b, q_bias, v_bias, p_qkv2);

    // 4) fused windowed attention (bf16 hi/lo compensated mma.sync)
    attn_kernel<<<dim3(NWIN, HEADS), 256, ATTN_SMEM>>>(p_qkv2, p_att);

    // 5) out = att @ w_proj  (mma.sync tf32)
    tgemm<<<dim3(Cc / 128, NPIX / 128), 256, TG_SMEM_B>>>(p_att, p_wprojT, out, Cc);
}

// round 16
// speedup vs baseline: 2.4872x; 1.1851x over previous
#include <cuda_runtime.h>
#include <cuda_bf16.h>
#include <cstdint>
#include <cstddef>

#define Bc 2
#define Hc 128
#define Wc 128
#define Cc 256
#define C3 768
#define NPIX (Bc*Hc*Wc)           // 32768
#define HEADS 8
#define HD 32
#define WS 8
#define KW 16
#define NWIN 512                  // B * 16 * 16
#define GK 256                    // GEMM K (both GEMMs)

// tgemm smem: [128 rows][36 floats] per operand per stage
#define TS_ROW 36
#define TG_STAGE_F (2 * 128 * TS_ROW)
#define TG_SMEM_B  (2 * TG_STAGE_F * 4)        // 73728 bytes

// ---- attn smem word-offsets ----
// raw region (reused as merge buffer at the end):
#define O_QRAW 0        // Qraw[64][36] f32   (2304)
#define O_KRAW 2304     // Kraw[128][36] f32  (4608)
#define O_VRAW 6912     // Vraw[128][40] f32  (5120) -> raw ends 12032
#define O_OMRG 0        // merge: [64 q][34]  (2176)
#define O_RS   2176     // merge rowsums [64]
// split region:
#define O_QHI  12032    // Qhi[64][20]
#define O_QLO  13312
#define O_KHI  14592    // Khi[128][20]
#define O_KLO  17152
#define O_VTHI 19712    // Vthi[32][68]
#define O_VTLO 21888
#define O_TAB  24064    // 529
#define ATTN_WORDS 24593
#define KQW 20
#define PVW 68

// ---------------- scratch (device globals; no allocation) ----------------
__device__ __align__(16) float g_qkv [(size_t)NPIX * C3];
__device__ __align__(16) float g_qkv2[(size_t)NPIX * C3];
__device__ __align__(16) float g_att [(size_t)NPIX * Cc];
__device__ __align__(16) float g_wqkvT[(size_t)C3 * Cc];
__device__ __align__(16) float g_wprojT[(size_t)Cc * Cc];
__device__ __align__(16) float g_bias_tab[8 * 529];
__device__ float g_scale[8];

// ---------------- helpers ----------------
__device__ __forceinline__ uint32_t smem_u32(const void* p) {
    uint32_t a;
    asm("{ .reg .u64 t; cvta.to.shared.u64 t, %1; cvt.u32.u64 %0, t; }" : "=r"(a) : "l"(p));
    return a;
}
__device__ __forceinline__ uint32_t to_tf32(float f) {
    uint32_t r;
    asm("cvt.rna.tf32.f32 %0, %1;" : "=r"(r) : "f"(f));
    return r;
}
__device__ __forceinline__ void bf16_split2(float a, float b, uint32_t& hi, uint32_t& lo) {
    __nv_bfloat162 h = __floats2bfloat162_rn(a, b);
    float ra = a - __bfloat162float(h.x);
    float rb = b - __bfloat162float(h.y);
    __nv_bfloat162 l = __floats2bfloat162_rn(ra, rb);
    hi = *reinterpret_cast<uint32_t*>(&h);
    lo = *reinterpret_cast<uint32_t*>(&l);
}
#define MMA_TF32(c, a0,a1,a2,a3, b0,b1) \
    asm volatile("mma.sync.aligned.m16n8k8.row.col.f32.tf32.tf32.f32 " \
        "{%0,%1,%2,%3}, {%4,%5,%6,%7}, {%8,%9}, {%0,%1,%2,%3};" \
        : "+f"((c)[0]), "+f"((c)[1]), "+f"((c)[2]), "+f"((c)[3]) \
        : "r"(a0), "r"(a1), "r"(a2), "r"(a3), "r"(b0), "r"(b1))
#define MMA_BF16(c, a0,a1,a2,a3, b0,b1) \
    asm volatile("mma.sync.aligned.m16n8k16.row.col.f32.bf16.bf16.f32 " \
        "{%0,%1,%2,%3}, {%4,%5,%6,%7}, {%8,%9}, {%0,%1,%2,%3};" \
        : "+f"((c)[0]), "+f"((c)[1]), "+f"((c)[2]), "+f"((c)[3]) \
        : "r"(a0), "r"(a1), "r"(a2), "r"(a3), "r"(b0), "r"(b1))

#define CP_ASYNC16(dst, src) asm volatile("cp.async.cg.shared.global [%0], [%1], 16;" :: "r"(dst), "l"(src) : "memory")
#define CP_ASYNC16Z(dst, src, sz) asm volatile("cp.async.cg.shared.global [%0], [%1], 16, %2;" :: "r"(dst), "l"(src), "r"(sz) : "memory")
#define CP_COMMIT()          asm volatile("cp.async.commit_group;" ::: "memory")
#define CP_WAIT(n)           asm volatile("cp.async.wait_group %0;" :: "n"(n) : "memory")

// ---------------- weight transpose (tiny) ----------------
__global__ void transpose_kernel(const float* __restrict__ W, float* __restrict__ WT,
                                 int K, int N)
{
    int i = blockIdx.x * 256 + threadIdx.x;
    if (i >= K * N) return;
    int k = i / N, n = i % N;
    WT[(size_t)n * K + k] = W[i];
}

// ---------------- mma.sync tf32 GEMM: C[M,N] = A[M,GK] * Bt[N,GK]^T ----------------
__global__ __launch_bounds__(256, 2) void tgemm(const float* __restrict__ A,
                                                const float* __restrict__ Bt,
                                                float* __restrict__ C, int N)
{
    extern __shared__ float sm[];
    uint32_t sb = smem_u32(sm);

    int tid  = threadIdx.x;
    int wid  = tid >> 5, lane = tid & 31;
    int gid  = lane >> 2, tg = lane & 3;
    int wr   = wid >> 2, wcol = wid & 3;
    int bx = blockIdx.x, by = blockIdx.y;

    const float* Ab = A  + (size_t)(by * 128) * GK;
    const float* Bb = Bt + (size_t)(bx * 128) * GK;

    float c[4][4][4];
#pragma unroll
    for (int mt = 0; mt < 4; mt++)
#pragma unroll
        for (int nt = 0; nt < 4; nt++)
#pragma unroll
            for (int i = 0; i < 4; i++) c[mt][nt][i] = 0.f;

    int ld_row = tid >> 3, ld_c4 = tid & 7;

#define TG_ISSUE(kt) do { \
        int _bs = (kt) & 1; \
        uint32_t _ab = sb + _bs * (TG_STAGE_F * 4); \
        uint32_t _bbx = _ab + 128 * TS_ROW * 4; \
        const float* _ga = Ab + (kt) * 32; \
        const float* _gb = Bb + (kt) * 32; \
        _Pragma("unroll") \
        for (int _it = 0; _it < 4; _it++) { \
            int _row = ld_row + _it * 32; \
            uint32_t _off = (_row * TS_ROW + ld_c4 * 4) * 4; \
            CP_ASYNC16(_ab  + _off, _ga + (size_t)_row * GK + ld_c4 * 4); \
            CP_ASYNC16(_bbx + _off, _gb + (size_t)_row * GK + ld_c4 * 4); \
        } \
        CP_COMMIT(); \
    } while (0)

    TG_ISSUE(0);

    for (int kt = 0; kt < 8; kt++) {
        if (kt + 1 < 8) { TG_ISSUE(kt + 1); CP_WAIT(1); }
        else            { CP_WAIT(0); }
        __syncthreads();

        const float* Asb = sm + (kt & 1) * TG_STAGE_F;
        const float* Bsb = Asb + 128 * TS_ROW;

#pragma unroll
        for (int kk = 0; kk < 32; kk += 8) {
            uint32_t a[4][4], b[4][2];
#pragma unroll
            for (int mt = 0; mt < 4; mt++) {
                const float* ar = Asb + (wr * 64 + mt * 16 + gid) * TS_ROW + kk + tg;
                a[mt][0] = to_tf32(ar[0]);
                a[mt][1] = to_tf32(ar[8 * TS_ROW]);
                a[mt][2] = to_tf32(ar[4]);
                a[mt][3] = to_tf32(ar[8 * TS_ROW + 4]);
            }
#pragma unroll
            for (int nt = 0; nt < 4; nt++) {
                const float* br = Bsb + (wcol * 32 + nt * 8 + gid) * TS_ROW + kk + tg;
                b[nt][0] = to_tf32(br[0]);
                b[nt][1] = to_tf32(br[4]);
            }
#pragma unroll
            for (int mt = 0; mt < 4; mt++)
#pragma unroll
                for (int nt = 0; nt < 4; nt++)
                    MMA_TF32(c[mt][nt], a[mt][0], a[mt][1], a[mt][2], a[mt][3],
                             b[nt][0], b[nt][1]);
        }
        __syncthreads();
    }

#pragma unroll
    for (int mt = 0; mt < 4; mt++) {
        int row = by * 128 + wr * 64 + mt * 16 + gid;
#pragma unroll
        for (int nt = 0; nt < 4; nt++) {
            int col = bx * 128 + wcol * 32 + nt * 8 + 2 * tg;
            *reinterpret_cast<float2*>(&C[(size_t)row * N + col]) =
                make_float2(c[mt][nt][0], c[mt][nt][1]);
            *reinterpret_cast<float2*>(&C[(size_t)(row + 8) * N + col]) =
                make_float2(c[mt][nt][2], c[mt][nt][3]);
        }
    }
#undef TG_ISSUE
}

// ---------------- CPB MLP + per-head scale ----------------
__global__ void cpb_kernel(const float* __restrict__ w1, const float* __restrict__ b1,
                           const float* __restrict__ w2, const float* __restrict__ ls)
{
    int t = blockIdx.x * blockDim.x + threadIdx.x;
    if (t < 8) g_scale[t] = expf(fminf(ls[t], 4.605170185988091f)); // log(100)
    if (t >= 529) return;
    int a = t / 23, b = t % 23;
    float c0 = (float)(a - 11) * (8.0f / 7.0f);
    float c1 = (float)(b - 11) * (8.0f / 7.0f);
    const float inv_log8 = 0.4808983469629878f;
    float v0 = copysignf(log1pf(fabsf(c0)), c0) * inv_log8;
    float v1 = copysignf(log1pf(fabsf(c1)), c1) * inv_log8;
    float acc[8];
#pragma unroll
    for (int h = 0; h < 8; h++) acc[h] = 0.f;
    for (int j = 0; j < 512; j++) {
        float hv = fmaxf(fmaf(v0, w1[j], fmaf(v1, w1[512 + j], b1[j])), 0.f);
#pragma unroll
        for (int h = 0; h < 8; h++) acc[h] += hv * w2[j * 8 + h];
    }
#pragma unroll
    for (int h = 0; h < 8; h++)
        g_bias_tab[h * 529 + t] = 16.0f / (1.0f + expf(-acc[h]));
}

// ---------------- depthwise 3x3 conv + LayerNorm + bias: row-sweep register ring ----------------
__global__ __launch_bounds__(192) void convln_kernel(const float* __restrict__ qkv,
                                                     const float* __restrict__ wdw,
                                                     const float* __restrict__ lng,
                                                     const float* __restrict__ lnb,
                                                     const float* __restrict__ qb,
                                                     const float* __restrict__ vb,
                                                     float* __restrict__ out)
{
    int blk  = blockIdx.x;           // 512 = b(2) * h(128) * half(2)
    int half = blk & 1;
    int hh   = (blk >> 1) & 127;
    int b    = blk >> 8;
    int tid  = threadIdx.x;
    int c4   = tid * 4;
    int wid  = tid >> 5, lane = tid & 31;

    float4 wt[9];
#pragma unroll
    for (int i = 0; i < 9; i++)
        wt[i] = *reinterpret_cast<const float4*>(wdw + i * C3 + c4);
    float4 gv = *reinterpret_cast<const float4*>(lng + c4);
    float4 bb = *reinterpret_cast<const float4*>(lnb + c4);
    if (c4 < 256) {
        float4 qv = *reinterpret_cast<const float4*>(qb + c4);
        bb.x += qv.x; bb.y += qv.y; bb.z += qv.z; bb.w += qv.w;
    } else if (c4 >= 512) {
        float4 vv = *reinterpret_cast<const float4*>(vb + c4 - 512);
        bb.x += vv.x; bb.y += vv.y; bb.z += vv.z; bb.w += vv.w;
    }

    __shared__ float reds[2][6], redq[2][6];

    const float4 z4 = make_float4(0.f, 0.f, 0.f, 0.f);
    float4 ring[3][3];

#define LOADCOL(col, dst) do { \
        if ((col) < 0 || (col) > 127) { dst[0] = z4; dst[1] = z4; dst[2] = z4; } \
        else { \
            _Pragma("unroll") \
            for (int _i = 0; _i < 3; _i++) { \
                int _r = hh - 1 + _i; \
                dst[_i] = (_r >= 0 && _r <= 127) \
                    ? *reinterpret_cast<const float4*>(qkv + ((size_t)((b * 128 + _r) * 128 + (col))) * C3 + c4) \
                    : z4; \
            } \
        } \
    } while (0)

    int w0 = half * 64;
    LOADCOL(w0 - 1, ring[0]);
    LOADCOL(w0,     ring[1]);
    LOADCOL(w0 + 1, ring[2]);

    for (int w = w0; w < w0 + 64; w++) {
        // conv for current column using resident ring
        float4 acc = z4;
#pragma unroll
        for (int dc = 0; dc < 3; dc++)
#pragma unroll
            for (int dr = 0; dr < 3; dr++) {
                float4 xv = ring[dc][dr];
                float4 wv = wt[dr * 3 + dc];
                acc.x = fmaf(xv.x, wv.x, acc.x);
                acc.y = fmaf(xv.y, wv.y, acc.y);
                acc.z = fmaf(xv.z, wv.z, acc.z);
                acc.w = fmaf(xv.w, wv.w, acc.w);
            }

        // rotate + prefetch NEXT column before the reduction/sync (hides LDG latency)
        ring[0][0] = ring[1][0]; ring[0][1] = ring[1][1]; ring[0][2] = ring[1][2];
        ring[1][0] = ring[2][0]; ring[1][1] = ring[2][1]; ring[1][2] = ring[2][2];
        if (w + 1 < w0 + 64) LOADCOL(w + 2, ring[2]);

        float s  = acc.x + acc.y + acc.z + acc.w;
        float sq = acc.x * acc.x + acc.y * acc.y + acc.z * acc.z + acc.w * acc.w;
#pragma unroll
        for (int off = 16; off > 0; off >>= 1) {
            s  += __shfl_xor_sync(0xffffffffu, s,  off);
            sq += __shfl_xor_sync(0xffffffffu, sq, off);
        }
        int par = w & 1;
        if (lane == 0) { reds[par][wid] = s; redq[par][wid] = sq; }
        __syncthreads();
        float st = 0.f, sqt = 0.f;
#pragma unroll
        for (int i = 0; i < 6; i++) { st += reds[par][i]; sqt += redq[par][i]; }
        float mu   = st * (1.0f / 768.0f);
        float var  = sqt * (1.0f / 768.0f) - mu * mu;
        float rstd = rsqrtf(var + 1e-5f);

        float4 y;
        y.x = (acc.x - mu) * rstd * gv.x + bb.x;
        y.y = (acc.y - mu) * rstd * gv.y + bb.y;
        y.z = (acc.z - mu) * rstd * gv.z + bb.z;
        y.w = (acc.w - mu) * rstd * gv.w + bb.w;
        *reinterpret_cast<float4*>(out + ((size_t)((b * 128 + hh) * 128 + w)) * C3 + c4) = y;
    }
#undef LOADCOL
}

// ---------------- fused windowed cosine attention ----------------
// bf16 hi/lo compensated mma.sync; P stays in registers (S C-frag == PV A-frag);
// cp.async double-buffered K/V raw loads; per-warp partial O merged across wc2 pair.
__global__ __launch_bounds__(256) void attn_kernel(const float* __restrict__ qkv2,
                                                   float* __restrict__ out)
{
    extern __shared__ float smf[];
    uint32_t* smu = reinterpret_cast<uint32_t*>(smf);
    uint32_t sb = smem_u32(smf);

    int widx = blockIdx.x, h = blockIdx.y;
    int b    = widx >> 8;
    int wrow = (widx >> 4) & 15;
    int wcol = widx & 15;
    int tid  = threadIdx.x;
    int wid  = tid >> 5, lane = tid & 31;
    int gid  = lane >> 2, tg = lane & 3;
    int wr2  = wid >> 1, wc2 = wid & 1;
    int q0   = wr2 * 16;

    // ---- issue Q raw cp.async (group 0)
    for (int t = tid; t < 512; t += 256) {
        int q = t >> 3, d4 = (t & 7) << 2;
        int pr = wrow * 8 + (q >> 3), pc = wcol * 8 + (q & 7);
        const float* p = qkv2 + ((size_t)((b * 128 + pr) * 128 + pc)) * C3 + h * HD + d4;
        CP_ASYNC16(sb + (O_QRAW + q * 36 + d4) * 4, p);
    }
    CP_COMMIT();

    // ---- issue K/V raw for half 0 (group 1)
#define KV_ISSUE(half) do { \
        int _br = wrow * 8 - 4 + 8 * (half), _bc = wcol * 8 - 4; \
        for (int _i = tid; _i < 128 * 8; _i += 256) { \
            int _kl = _i >> 3, _d4 = (_i & 7) << 2; \
            int _gr = _br + (_kl >> 4), _gc = _bc + (_kl & 15); \
            int _in = (_gr >= 0 && _gr < 128 && _gc >= 0 && _gc < 128); \
            int _grc = min(max(_gr, 0), 127), _gcc = min(max(_gc, 0), 127); \
            const float* _p = qkv2 + ((size_t)((b * 128 + _grc) * 128 + _gcc)) * C3 + Cc + h * HD + _d4; \
            int _sz = _in ? 16 : 0; \
            CP_ASYNC16Z(sb + (O_KRAW + _kl * 36 + _d4) * 4, _p, _sz); \
            CP_ASYNC16Z(sb + (O_VRAW + _kl * 40 + _d4) * 4, _p + Cc, _sz); \
        } \
        CP_COMMIT(); \
    } while (0)

    KV_ISSUE(0);

    // ---- bias table load (overlaps cp.async)
    for (int t = tid; t < 529; t += 256) smf[O_TAB + t] = g_bias_tab[h * 529 + t];

    // ---- Q ready -> normalize*scale -> bf16 hi/lo split
    CP_WAIT(1);
    __syncthreads();
    if (tid < 64) {
        float v[32]; float ss = 0.f;
#pragma unroll
        for (int d = 0; d < 32; d++) { v[d] = smf[O_QRAW + tid * 36 + d]; ss = fmaf(v[d], v[d], ss); }
        float qm = rsqrtf(fmaxf(ss, 1.55e-5f)) * g_scale[h];
#pragma unroll
        for (int j = 0; j < 16; j++) {
            uint32_t hi, lo;
            bf16_split2(v[2 * j] * qm, v[2 * j + 1] * qm, hi, lo);
            smu[O_QHI + tid * KQW + j] = hi;
            smu[O_QLO + tid * KQW + j] = lo;
        }
    }

    float cO[4][4];     // per-warp partial O: 16q x 32d over this warp's 128 keys
#pragma unroll
    for (int n = 0; n < 4; n++)
#pragma unroll
        for (int i = 0; i < 4; i++) cO[n][i] = 0.f;
    float r0 = 0.f, r1 = 0.f;   // rowsum partials (accumulate across halves)

    for (int half = 0; half < 2; half++) {
        // raw K/V for this half ready
        CP_WAIT(0);
        __syncthreads();

        // ---- K normalize -> split (256 threads: 2 per row)
        {
            int row = tid >> 1, part = tid & 1;
            float v[16]; float ss = 0.f;
#pragma unroll
            for (int d = 0; d < 16; d++) {
                v[d] = smf[O_KRAW + row * 36 + part * 16 + d];
                ss = fmaf(v[d], v[d], ss);
            }
            ss += __shfl_xor_sync(0xffffffffu, ss, 1);
            float rm = rsqrtf(fmaxf(ss, 1.55e-5f));
#pragma unroll
            for (int j = 0; j < 8; j++) {
                uint32_t hi, lo;
                bf16_split2(v[2 * j] * rm, v[2 * j + 1] * rm, hi, lo);
                smu[O_KHI + row * KQW + part * 8 + j] = hi;
                smu[O_KLO + row * KQW + part * 8 + j] = lo;
            }
        }
        // ---- V transpose + split: Vt[d][key-pair]
        for (int i = tid; i < 32 * 64; i += 256) {
            int d  = i & 31;
            int k2 = i >> 5;
            float v0 = smf[O_VRAW + (2 * k2)     * 40 + d];
            float v1 = smf[O_VRAW + (2 * k2 + 1) * 40 + d];
            uint32_t hi, lo;
            bf16_split2(v0, v1, hi, lo);
            smu[O_VTHI + d * PVW + k2] = hi;
            smu[O_VTLO + d * PVW + k2] = lo;
        }
        __syncthreads();   // splits ready; raw region fully consumed

        // ---- prefetch next half's raw K/V (overlaps S/exp/PV)
        if (half == 0) KV_ISSUE(1);

        // ---- S phase: 16q x 64k per warp (keys wc2*64..)
        float cs[8][4];
#pragma unroll
        for (int t = 0; t < 8; t++)
#pragma unroll
            for (int i = 0; i < 4; i++) cs[t][i] = 0.f;

#pragma unroll
        for (int ks = 0; ks < 2; ks++) {
            int w0 = ks * 8 + tg;
            uint32_t ah[4], al[4];
            ah[0] = smu[O_QHI + (q0 + gid)     * KQW + w0];
            ah[1] = smu[O_QHI + (q0 + gid + 8) * KQW + w0];
            ah[2] = smu[O_QHI + (q0 + gid)     * KQW + w0 + 4];
            ah[3] = smu[O_QHI + (q0 + gid + 8) * KQW + w0 + 4];
            al[0] = smu[O_QLO + (q0 + gid)     * KQW + w0];
            al[1] = smu[O_QLO + (q0 + gid + 8) * KQW + w0];
            al[2] = smu[O_QLO + (q0 + gid)     * KQW + w0 + 4];
            al[3] = smu[O_QLO + (q0 + gid + 8) * KQW + w0 + 4];
#pragma unroll
            for (int t = 0; t < 8; t++) {
                int n0 = wc2 * 64 + t * 8;
                uint32_t bh0 = smu[O_KHI + (n0 + gid) * KQW + w0];
                uint32_t bh1 = smu[O_KHI + (n0 + gid) * KQW + w0 + 4];
                uint32_t bl0 = smu[O_KLO + (n0 + gid) * KQW + w0];
                uint32_t bl1 = smu[O_KLO + (n0 + gid) * KQW + w0 + 4];
                MMA_BF16(cs[t], ah[0], ah[1], ah[2], ah[3], bh0, bh1);
                MMA_BF16(cs[t], ah[0], ah[1], ah[2], ah[3], bl0, bl1);
                MMA_BF16(cs[t], al[0], al[1], al[2], al[3], bh0, bh1);
            }
        }

        // ---- bias + exp in registers + rowsum partials
        int qa = q0 + gid, qb_ = qa + 8;
        int qra = qa >> 3, qca = qa & 7;
        int qrb = qb_ >> 3, qcb = qb_ & 7;
#pragma unroll
        for (int t = 0; t < 8; t++) {
            int kl0 = wc2 * 64 + t * 8 + 2 * tg;
#pragma unroll
            for (int e = 0; e < 2; e++) {
                int kl = kl0 + e;
                int kr = (kl >> 4) + 8 * half, kc = kl & 15;
                float bias_a = smf[O_TAB + (qra - kr + 15) * 23 + (qca - kc + 15)];
                float bias_b = smf[O_TAB + (qrb - kr + 15) * 23 + (qcb - kc + 15)];
                float pa = __expf(cs[t][e]     + bias_a - 16.0f);
                float pb = __expf(cs[t][e + 2] + bias_b - 16.0f);
                cs[t][e]     = pa;  r0 += pa;
                cs[t][e + 2] = pb;  r1 += pb;
            }
        }

        // ---- PV phase: P from registers (C-frag == A-frag), B = Vt splits
#pragma unroll
        for (int s = 0; s < 4; s++) {
            uint32_t ah[4], al[4];
            bf16_split2(cs[2*s][0],     cs[2*s][1],     ah[0], al[0]);
            bf16_split2(cs[2*s][2],     cs[2*s][3],     ah[1], al[1]);
            bf16_split2(cs[2*s + 1][0], cs[2*s + 1][1], ah[2], al[2]);
            bf16_split2(cs[2*s + 1][2], cs[2*s + 1][3], ah[3], al[3]);
            int w0 = wc2 * 32 + s * 8 + tg;
#pragma unroll
            for (int n = 0; n < 4; n++) {
                int d0 = n * 8;
                uint32_t bh0 = smu[O_VTHI + (d0 + gid) * PVW + w0];
                uint32_t bh1 = smu[O_VTHI + (d0 + gid) * PVW + w0 + 4];
                uint32_t bl0 = smu[O_VTLO + (d0 + gid) * PVW + w0];
                uint32_t bl1 = smu[O_VTLO + (d0 + gid) * PVW + w0 + 4];
                MMA_BF16(cO[n], ah[0], ah[1], ah[2], ah[3], bh0, bh1);
                MMA_BF16(cO[n], ah[0], ah[1], ah[2], ah[3], bl0, bl1);
                MMA_BF16(cO[n], al[0], al[1], al[2], al[3], bh0, bh1);
            }
        }
    }

    // ---- rowsum reduce over tg
    r0 += __shfl_xor_sync(0xffffffffu, r0, 1);
    r0 += __shfl_xor_sync(0xffffffffu, r0, 2);
    r1 += __shfl_xor_sync(0xffffffffu, r1, 1);
    r1 += __shfl_xor_sync(0xffffffffu, r1, 2);

    // ---- merge wc2 pair via raw region (now dead)
    __syncthreads();
    int qa = q0 + gid, qb_ = qa + 8;
    if (wc2 == 1) {
#pragma unroll
        for (int n = 0; n < 4; n++) {
            int d = n * 8 + 2 * tg;
            *reinterpret_cast<float2*>(&smf[O_OMRG + qa  * 34 + d]) = make_float2(cO[n][0], cO[n][1]);
            *reinterpret_cast<float2*>(&smf[O_OMRG + qb_ * 34 + d]) = make_float2(cO[n][2], cO[n][3]);
        }
        if (tg == 0) { smf[O_RS + qa] = r0; smf[O_RS + qb_] = r1; }
    }
    __syncthreads();
    if (wc2 == 0) {
        float linv0 = 1.0f / (r0 + smf[O_RS + qa]);
        float linv1 = 1.0f / (r1 + smf[O_RS + qb_]);
        int pra = wrow * 8 + (qa >> 3),  pca = wcol * 8 + (qa & 7);
        int prb = wrow * 8 + (qb_ >> 3), pcb = wcol * 8 + (qb_ & 7);
        float* opa = out + ((size_t)((b * 128 + pra) * 128 + pca)) * Cc + h * HD;
        float* opb = out + ((size_t)((b * 128 + prb) * 128 + pcb)) * Cc + h * HD;
#pragma unroll
        for (int n = 0; n < 4; n++) {
            int d = n * 8 + 2 * tg;
            float2 wa = *reinterpret_cast<const float2*>(&smf[O_OMRG + qa  * 34 + d]);
            float2 wb = *reinterpret_cast<const float2*>(&smf[O_OMRG + qb_ * 34 + d]);
            *reinterpret_cast<float2*>(opa + d) =
                make_float2((cO[n][0] + wa.x) * linv0, (cO[n][1] + wa.y) * linv0);
            *reinterpret_cast<float2*>(opb + d) =
                make_float2((cO[n][2] + wb.x) * linv1, (cO[n][3] + wb.y) * linv1);
        }
    }
#undef KV_ISSUE
}

// ---------------- launch ----------------
extern "C" void kernel_launch(void* const* d_in, const int* in_sizes, int n_in,
                              void* d_out, int out_size)
{
    const float* x           = (const float*)d_in[0];
    const float* w_qkv       = (const float*)d_in[1];
    const float* w_dw        = (const float*)d_in[2];
    const float* ln_g        = (const float*)d_in[3];
    const float* ln_b        = (const float*)d_in[4];
    const float* q_bias      = (const float*)d_in[5];
    const float* v_bias      = (const float*)d_in[6];
    const float* logit_scale = (const float*)d_in[7];
    const float* cpb_w1      = (const float*)d_in[8];
    const float* cpb_b1      = (const float*)d_in[9];
    const float* cpb_w2      = (const float*)d_in[10];
    const float* w_proj      = (const float*)d_in[11];
    float* out = (float*)d_out;

    float *p_qkv, *p_qkv2, *p_att, *p_wqkvT, *p_wprojT;
    cudaGetSymbolAddress((void**)&p_qkv,   g_qkv);
    cudaGetSymbolAddress((void**)&p_qkv2,  g_qkv2);
    cudaGetSymbolAddress((void**)&p_att,   g_att);
    cudaGetSymbolAddress((void**)&p_wqkvT, g_wqkvT);
    cudaGetSymbolAddress((void**)&p_wprojT,g_wprojT);

    const int ATTN_SMEM = ATTN_WORDS * 4;   // 98372 B
    cudaFuncSetAttribute(attn_kernel, cudaFuncAttributeMaxDynamicSharedMemorySize, ATTN_SMEM);
    cudaFuncSetAttribute(tgemm, cudaFuncAttributeMaxDynamicSharedMemorySize, TG_SMEM_B);

    // 0) transpose weights to [N][K] K-major
    transpose_kernel<<<(Cc * C3 + 255) / 256, 256>>>(w_qkv, p_wqkvT, Cc, C3);
    transpose_kernel<<<(Cc * Cc + 255) / 256, 256>>>(w_proj, p_wprojT, Cc, Cc);

    // 1) CPB bias table + per-head scales
    cpb_kernel<<<5, 128>>>(cpb_w1, cpb_b1, cpb_w2, logit_scale);

    // 2) qkv = x @ w_qkv  (mma.sync tf32)
    tgemm<<<dim3(C3 / 128, NPIX / 128), 256, TG_SMEM_B>>>(x, p_wqkvT, p_qkv, C3);

    // 3) depthwise conv + LN + bias (row-sweep, prefetch-hidden)
    convln_kernel<<<512, 192>>>(p_qkv, w_dw, ln_g, ln_b, q_bias, v_bias, p_qkv2);

    // 4) fused windowed attention (register-P, cp.async pipelined)
    attn_kernel<<<dim3(NWIN, HEADS), 256, ATTN_SMEM>>>(p_qkv2, p_att);

    // 5) out = att @ w_proj  (mma.sync tf32)
    tgemm<<<dim3(Cc / 128, NPIX / 128), 256, TG_SMEM_B>>>(p_att, p_wprojT, out, Cc);
}